// round 9
// baseline (speedup 1.0000x reference)
#include <cuda_runtime.h>

// Problem constants
#define Bn 4
#define Tn 2048
#define Sn 2048
#define Cn 256
#define En 512
#define Hn 8
#define Dn 64
#define SCALE_F 0.04419417382415922f   // 512^-0.5

// ---------------- scratch (static device globals; no allocations) ----------
// Referenced ONLY from device code. g_Q doubles as the attention output
// buffer (in-place; each attn thread reads its own Q slice into registers
// before overwriting it at the end).
__device__ float g_Q[Bn * Tn * En];     // pre-scaled Q, then attention out
__device__ float g_K[Bn * Sn * En];     // [B*S, E]
__device__ float g_V[Bn * Sn * En];     // [B*S, E]
__device__ float g_Wc[En * Cn];         // wq @ w_in
__device__ float g_bc[En];              // bq + wq @ b_in
__device__ int   g_mask_type;           // 0=int32 words, 1=float32 words, 2=bytes

// ---------------- mask dtype detection -------------------------------------
__global__ void detect_mask_kernel(const void* __restrict__ mask, int nelem) {
    __shared__ int s_notint, s_notfloat;
    if (threadIdx.x == 0) { s_notint = 0; s_notfloat = 0; }
    __syncthreads();
    int n = nelem < 4096 ? nelem : 4096;
    const unsigned int* w = (const unsigned int*)mask;
    int ni = 0, nf = 0;
    for (int i = threadIdx.x; i < n; i += blockDim.x) {
        unsigned int v = w[i];
        if (v > 1u) ni = 1;
        if (v != 0u && v != 0x3F800000u) nf = 1;
    }
    if (ni) atomicOr(&s_notint, 1);
    if (nf) atomicOr(&s_notfloat, 1);
    __syncthreads();
    if (threadIdx.x == 0)
        g_mask_type = (s_notint == 0) ? 0 : (s_notfloat == 0 ? 1 : 2);
}

// ---------------- fold wq @ w_in -------------------------------------------
__global__ void combine_weights_kernel(const float* __restrict__ wq,
                                       const float* __restrict__ w_in,
                                       const float* __restrict__ b_in,
                                       const float* __restrict__ bq) {
    int e = blockIdx.x;      // 0..E-1
    int c = threadIdx.x;     // 0..C-1
    float acc = 0.f;
    #pragma unroll 4
    for (int j = 0; j < En; j++)
        acc = fmaf(wq[e * En + j], w_in[j * Cn + c], acc);
    g_Wc[e * Cn + c] = acc;
    if (c == 0) {
        float a = bq[e];
        for (int j = 0; j < En; j++)
            a = fmaf(wq[e * En + j], b_in[j], a);
        g_bc[e] = a;
    }
}

// ---------------- tiled NT GEMM with bias -----------------------------------
// C[m,n] = alpha * ( sum_k A[m,k]*B[n,k] + bias[n] )
// All scratch-global wiring happens HERE, in device code (host never touches
// __device__ symbols):
//   MODE 0: A=param(x),       B=g_Wc,  bias=g_bc,  C=g_Q,  alpha=SCALE
//   MODE 1: A=param(context), B=param, bias=param, C=g_K
//   MODE 2: A=param(context), B=param, bias=param, C=g_V
//   MODE 3: A=g_Q (attn out), B=param, bias=param, C=param(out)
template<int MODE>
__global__ __launch_bounds__(256)
void gemm_nt_bias(const float* __restrict__ A_in, const float* __restrict__ B_in,
                  const float* __restrict__ bias_in, float* __restrict__ C_out,
                  int M, int N, int K, float alpha) {
    const float* A    = (MODE == 3) ? (const float*)g_Q : A_in;
    const float* B    = (MODE == 0) ? (const float*)g_Wc : B_in;
    const float* bias = (MODE == 0) ? (const float*)g_bc : bias_in;
    float* C;
    if      (MODE == 0) C = g_Q;
    else if (MODE == 1) C = g_K;
    else if (MODE == 2) C = g_V;
    else                C = C_out;

    const int BM = 64, BN = 64, BK = 16;
    __shared__ float As[BK][BM];
    __shared__ float Bs[BK][BN];
    int tid = threadIdx.x;
    int tx = tid & 15;          // 0..15
    int ty = tid >> 4;          // 0..15
    int bm = blockIdx.y * BM;
    int bn = blockIdx.x * BN;
    int la_row = tid >> 2;          // 0..63
    int la_col = (tid & 3) * 4;     // 0,4,8,12

    float acc[4][4] = {};
    const float* Ap = A + (long)(bm + la_row) * K + la_col;
    const float* Bp = B + (long)(bn + la_row) * K + la_col;

    for (int k0 = 0; k0 < K; k0 += BK) {
        float4 av = *(const float4*)(Ap + k0);
        float4 bv = *(const float4*)(Bp + k0);
        As[la_col + 0][la_row] = av.x; As[la_col + 1][la_row] = av.y;
        As[la_col + 2][la_row] = av.z; As[la_col + 3][la_row] = av.w;
        Bs[la_col + 0][la_row] = bv.x; Bs[la_col + 1][la_row] = bv.y;
        Bs[la_col + 2][la_row] = bv.z; Bs[la_col + 3][la_row] = bv.w;
        __syncthreads();
        #pragma unroll
        for (int kk = 0; kk < BK; kk++) {
            float4 a4 = *(const float4*)&As[kk][ty * 4];
            float4 b4 = *(const float4*)&Bs[kk][tx * 4];
            float a[4] = {a4.x, a4.y, a4.z, a4.w};
            float b[4] = {b4.x, b4.y, b4.z, b4.w};
            #pragma unroll
            for (int i = 0; i < 4; i++)
                #pragma unroll
                for (int j = 0; j < 4; j++)
                    acc[i][j] = fmaf(a[i], b[j], acc[i][j]);
        }
        __syncthreads();
    }
    float bb[4];
    #pragma unroll
    for (int j = 0; j < 4; j++) bb[j] = bias[bn + tx * 4 + j];
    #pragma unroll
    for (int i = 0; i < 4; i++) {
        float4 r;
        r.x = alpha * (acc[i][0] + bb[0]);
        r.y = alpha * (acc[i][1] + bb[1]);
        r.z = alpha * (acc[i][2] + bb[2]);
        r.w = alpha * (acc[i][3] + bb[3]);
        *(float4*)&C[(long)(bm + ty * 4 + i) * N + bn + tx * 4] = r;
    }
}

// ---------------- flash attention -------------------------------------------
// grid: (T/64, B*H), block: 64 threads. One query row per thread.
// Reads g_Q/g_K/g_V, writes result in place over g_Q (own slice only).
// NOTE: no min-blocks bound — q[16]+o[16] float4 = 128 live fp32 values;
// a 128-reg cap (64thr x 8 blocks) would force accumulator spills.
__global__ __launch_bounds__(64)
void attn_kernel(const void* __restrict__ mask) {
    const int bh = blockIdx.y;
    const int b = bh / Hn, h = bh % Hn;
    const int t = blockIdx.x * 64 + threadIdx.x;
    const int lane = threadIdx.x;

    __shared__ float4 Ks[64][16];
    __shared__ float4 Vs[64][16];

    // Q row (pre-scaled) into registers
    float4 q[16];
    const float4* qp = (const float4*)(g_Q + (long)(b * Tn + t) * En + h * Dn);
    #pragma unroll
    for (int i = 0; i < 16; i++) q[i] = qp[i];

    float4 o[16];
    #pragma unroll
    for (int i = 0; i < 16; i++) o[i] = make_float4(0.f, 0.f, 0.f, 0.f);
    float m = -1e30f, l = 0.f;
    const int mtype = g_mask_type;

    #pragma unroll 1
    for (int s0 = 0; s0 < Sn; s0 += 64) {
        // pack this thread's 64 mask flags into bits (no smem involved)
        unsigned long long mb = 0ull;
        long mbase = (long)b * Tn * Sn + (long)t * Sn + s0;
        if (mtype == 2) {
            const unsigned long long* mp =
                (const unsigned long long*)((const unsigned char*)mask + mbase);
            #pragma unroll
            for (int w = 0; w < 8; w++) {
                unsigned long long v = mp[w];
                #pragma unroll
                for (int k = 0; k < 8; k++)
                    if ((v >> (8 * k)) & 0xffull) mb |= 1ull << (w * 8 + k);
            }
        } else {
            const int4* mp = (const int4*)((const int*)mask + mbase);
            #pragma unroll
            for (int w = 0; w < 16; w++) {
                int4 v = mp[w];
                if (v.x) mb |= 1ull << (w * 4 + 0);
                if (v.y) mb |= 1ull << (w * 4 + 1);
                if (v.z) mb |= 1ull << (w * 4 + 2);
                if (v.w) mb |= 1ull << (w * 4 + 3);
            }
        }

        __syncthreads();
        // cooperative K/V tile load: 1024 float4 each, 16 per thread
        #pragma unroll
        for (int p = 0; p < 16; p++) {
            int idx = p * 64 + lane;
            int row = idx >> 4;
            int col = idx & 15;
            long g = (long)(b * Sn + s0 + row) * En + h * Dn;
            Ks[row][col] = ((const float4*)(g_K + g))[col];
            Vs[row][col] = ((const float4*)(g_V + g))[col];
        }
        __syncthreads();

        #pragma unroll 2
        for (int j = 0; j < 64; j++) {
            float4 a = make_float4(0.f, 0.f, 0.f, 0.f);
            #pragma unroll
            for (int i = 0; i < 16; i++) {
                float4 kv = Ks[j][i];
                a.x = fmaf(q[i].x, kv.x, a.x);
                a.y = fmaf(q[i].y, kv.y, a.y);
                a.z = fmaf(q[i].z, kv.z, a.z);
                a.w = fmaf(q[i].w, kv.w, a.w);
            }
            float s = (a.x + a.y) + (a.z + a.w);
            if ((mb >> j) & 1ull) s = -1e9f;
            float mn = fmaxf(m, s);
            if (mn > m) {
                float corr = __expf(m - mn);
                l *= corr;
                #pragma unroll
                for (int i = 0; i < 16; i++) {
                    o[i].x *= corr; o[i].y *= corr;
                    o[i].z *= corr; o[i].w *= corr;
                }
                m = mn;
            }
            float p = __expf(s - m);
            l += p;
            #pragma unroll
            for (int i = 0; i < 16; i++) {
                float4 vv = Vs[j][i];
                o[i].x = fmaf(p, vv.x, o[i].x);
                o[i].y = fmaf(p, vv.y, o[i].y);
                o[i].z = fmaf(p, vv.z, o[i].z);
                o[i].w = fmaf(p, vv.w, o[i].w);
            }
        }
    }

    float inv = 1.f / l;
    float4* op = (float4*)(g_Q + (long)(b * Tn + t) * En + h * Dn);
    #pragma unroll
    for (int i = 0; i < 16; i++) {
        float4 r = o[i];
        r.x *= inv; r.y *= inv; r.z *= inv; r.w *= inv;
        op[i] = r;
    }
}

// ---------------- launch -----------------------------------------------------
// Host body: six plain kernel launches, no CUDA API calls, no __device__
// symbol references.
extern "C" void kernel_launch(void* const* d_in, const int* in_sizes, int n_in,
                              void* d_out, int out_size) {
    const float* x       = (const float*)d_in[0];   // [B,T,C]
    const float* context = (const float*)d_in[1];   // [B,S,E]
    const void*  pmask   = d_in[2];                 // [B,T,S] (dtype detected)
    const float* w_in    = (const float*)d_in[3];   // [E,C]
    const float* b_in    = (const float*)d_in[4];   // [E]
    const float* wq      = (const float*)d_in[5];   // [E,E]
    const float* bq      = (const float*)d_in[6];
    const float* wk      = (const float*)d_in[7];
    const float* bk      = (const float*)d_in[8];
    const float* wv      = (const float*)d_in[9];
    const float* bv      = (const float*)d_in[10];
    const float* w_out   = (const float*)d_in[11];  // [C,E]
    const float* b_out   = (const float*)d_in[12];  // [C]
    float* out = (float*)d_out;

    detect_mask_kernel<<<1, 256>>>(pmask, in_sizes[2]);
    combine_weights_kernel<<<En, Cn>>>(wq, w_in, b_in, bq);

    // Q = SCALE * (x @ Wc^T + bc) -> g_Q   [8192,512], K=256
    {
        dim3 g(En / 64, (Bn * Tn) / 64);
        gemm_nt_bias<0><<<g, 256>>>(x, nullptr, nullptr, nullptr,
                                    Bn * Tn, En, Cn, SCALE_F);
    }
    // K/V = context @ w^T + b -> g_K / g_V   [8192,512], K=512
    {
        dim3 g(En / 64, (Bn * Sn) / 64);
        gemm_nt_bias<1><<<g, 256>>>(context, wk, bk, nullptr,
                                    Bn * Sn, En, En, 1.f);
        gemm_nt_bias<2><<<g, 256>>>(context, wv, bv, nullptr,
                                    Bn * Sn, En, En, 1.f);
    }
    // attention (in place over g_Q)
    {
        dim3 g(Tn / 64, Bn * Hn);
        attn_kernel<<<g, 64>>>(pmask);
    }
    // out = O @ w_out^T + b_out   [8192,256], K=512
    {
        dim3 g(Cn / 64, (Bn * Tn) / 64);
        gemm_nt_bias<3><<<g, 256>>>(nullptr, w_out, b_out, out,
                                    Bn * Tn, Cn, En, 1.f);
    }
}

// round 11
// speedup vs baseline: 1.0660x; 1.0660x over previous
#include <cuda_runtime.h>

// Problem constants
#define Bn 4
#define Tn 2048
#define Sn 2048
#define Cn 256
#define En 512
#define Hn 8
#define Dn 64
#define SCALE_F 0.04419417382415922f   // 512^-0.5

typedef unsigned long long u64t;

// ---------------- packed f32x2 helpers (sm_100+: double-rate fp32) ----------
__device__ __forceinline__ u64t fma2(u64t a, u64t b, u64t c) {
    u64t d; asm("fma.rn.f32x2 %0, %1, %2, %3;" : "=l"(d) : "l"(a), "l"(b), "l"(c));
    return d;
}
__device__ __forceinline__ u64t mul2(u64t a, u64t b) {
    u64t d; asm("mul.rn.f32x2 %0, %1, %2;" : "=l"(d) : "l"(a), "l"(b));
    return d;
}
__device__ __forceinline__ u64t pack2(float lo, float hi) {
    u64t d; asm("mov.b64 %0, {%1, %2};" : "=l"(d) : "f"(lo), "f"(hi));
    return d;
}
__device__ __forceinline__ float2 unpack2(u64t v) {
    float lo, hi; asm("mov.b64 {%0, %1}, %2;" : "=f"(lo), "=f"(hi) : "l"(v));
    return make_float2(lo, hi);
}

// ---------------- scratch (static device globals; no allocations) ----------
// Referenced ONLY from device code. g_Q doubles as the attention output
// buffer (in-place; each attn thread reads its own Q slice into registers
// before overwriting it at the end).
__device__ float g_Q[Bn * Tn * En];     // pre-scaled Q, then attention out
__device__ float g_K[Bn * Sn * En];     // [B*S, E]
__device__ float g_V[Bn * Sn * En];     // [B*S, E]
__device__ float g_Wc[En * Cn];         // wq @ w_in
__device__ float g_bc[En];              // bq + wq @ b_in
__device__ int   g_mask_type;           // 0=int32 words, 1=float32 words, 2=bytes

// ---------------- mask dtype detection -------------------------------------
__global__ void detect_mask_kernel(const void* __restrict__ mask, int nelem) {
    __shared__ int s_notint, s_notfloat;
    if (threadIdx.x == 0) { s_notint = 0; s_notfloat = 0; }
    __syncthreads();
    int n = nelem < 4096 ? nelem : 4096;
    const unsigned int* w = (const unsigned int*)mask;
    int ni = 0, nf = 0;
    for (int i = threadIdx.x; i < n; i += blockDim.x) {
        unsigned int v = w[i];
        if (v > 1u) ni = 1;
        if (v != 0u && v != 0x3F800000u) nf = 1;
    }
    if (ni) atomicOr(&s_notint, 1);
    if (nf) atomicOr(&s_notfloat, 1);
    __syncthreads();
    if (threadIdx.x == 0)
        g_mask_type = (s_notint == 0) ? 0 : (s_notfloat == 0 ? 1 : 2);
}

// ---------------- fold wq @ w_in -------------------------------------------
__global__ void combine_weights_kernel(const float* __restrict__ wq,
                                       const float* __restrict__ w_in,
                                       const float* __restrict__ b_in,
                                       const float* __restrict__ bq) {
    int e = blockIdx.x;      // 0..E-1
    int c = threadIdx.x;     // 0..C-1
    float acc = 0.f;
    #pragma unroll 4
    for (int j = 0; j < En; j++)
        acc = fmaf(wq[e * En + j], w_in[j * Cn + c], acc);
    g_Wc[e * Cn + c] = acc;
    if (c == 0) {
        float a = bq[e];
        for (int j = 0; j < En; j++)
            a = fmaf(wq[e * En + j], b_in[j], a);
        g_bc[e] = a;
    }
}

// ---------------- tiled NT GEMM with bias -----------------------------------
// C[m,n] = alpha * ( sum_k A[m,k]*B[n,k] + bias[n] )
//   MODE 0: A=param(x),       B=g_Wc,  bias=g_bc,  C=g_Q,  alpha=SCALE
//   MODE 1: A=param(context), B=param, bias=param, C=g_K
//   MODE 2: A=param(context), B=param, bias=param, C=g_V
//   MODE 3: A=g_Q (attn out), B=param, bias=param, C=param(out)
template<int MODE>
__global__ __launch_bounds__(256)
void gemm_nt_bias(const float* __restrict__ A_in, const float* __restrict__ B_in,
                  const float* __restrict__ bias_in, float* __restrict__ C_out,
                  int M, int N, int K, float alpha) {
    const float* A    = (MODE == 3) ? (const float*)g_Q : A_in;
    const float* B    = (MODE == 0) ? (const float*)g_Wc : B_in;
    const float* bias = (MODE == 0) ? (const float*)g_bc : bias_in;
    float* C;
    if      (MODE == 0) C = g_Q;
    else if (MODE == 1) C = g_K;
    else if (MODE == 2) C = g_V;
    else                C = C_out;

    const int BM = 64, BN = 64, BK = 16;
    __shared__ float As[BK][BM];
    __shared__ float Bs[BK][BN];
    int tid = threadIdx.x;
    int tx = tid & 15;          // 0..15
    int ty = tid >> 4;          // 0..15
    int bm = blockIdx.y * BM;
    int bn = blockIdx.x * BN;
    int la_row = tid >> 2;          // 0..63
    int la_col = (tid & 3) * 4;     // 0,4,8,12

    float acc[4][4] = {};
    const float* Ap = A + (long)(bm + la_row) * K + la_col;
    const float* Bp = B + (long)(bn + la_row) * K + la_col;

    for (int k0 = 0; k0 < K; k0 += BK) {
        float4 av = *(const float4*)(Ap + k0);
        float4 bv = *(const float4*)(Bp + k0);
        As[la_col + 0][la_row] = av.x; As[la_col + 1][la_row] = av.y;
        As[la_col + 2][la_row] = av.z; As[la_col + 3][la_row] = av.w;
        Bs[la_col + 0][la_row] = bv.x; Bs[la_col + 1][la_row] = bv.y;
        Bs[la_col + 2][la_row] = bv.z; Bs[la_col + 3][la_row] = bv.w;
        __syncthreads();
        #pragma unroll
        for (int kk = 0; kk < BK; kk++) {
            float4 a4 = *(const float4*)&As[kk][ty * 4];
            float4 b4 = *(const float4*)&Bs[kk][tx * 4];
            float a[4] = {a4.x, a4.y, a4.z, a4.w};
            float b[4] = {b4.x, b4.y, b4.z, b4.w};
            #pragma unroll
            for (int i = 0; i < 4; i++)
                #pragma unroll
                for (int j = 0; j < 4; j++)
                    acc[i][j] = fmaf(a[i], b[j], acc[i][j]);
        }
        __syncthreads();
    }
    float bb[4];
    #pragma unroll
    for (int j = 0; j < 4; j++) bb[j] = bias[bn + tx * 4 + j];
    #pragma unroll
    for (int i = 0; i < 4; i++) {
        float4 r;
        r.x = alpha * (acc[i][0] + bb[0]);
        r.y = alpha * (acc[i][1] + bb[1]);
        r.z = alpha * (acc[i][2] + bb[2]);
        r.w = alpha * (acc[i][3] + bb[3]);
        *(float4*)&C[(long)(bm + ty * 4 + i) * N + bn + tx * 4] = r;
    }
}

// ---------------- flash attention (packed f32x2 math) -----------------------
// grid: (T/64, B*H), block: 64 threads. One query row per thread.
// All inner-loop FMA work uses fma.rn.f32x2 (2 fp32 lanes per FMA-pipe op,
// IEEE fp32 rounding per lane). Reads g_Q/g_K/g_V, writes in place over g_Q.
__global__ __launch_bounds__(64)
void attn_kernel(const void* __restrict__ mask) {
    const int bh = blockIdx.y;
    const int b = bh / Hn, h = bh % Hn;
    const int t = blockIdx.x * 64 + threadIdx.x;
    const int lane = threadIdx.x;

    __shared__ ulonglong2 Ks[64][16];   // 64 rows x 64 floats (as f32x2 pairs)
    __shared__ ulonglong2 Vs[64][16];

    // Q row (pre-scaled) into packed registers: 32 f32x2 pairs
    u64t q2[32];
    {
        const ulonglong2* qp =
            (const ulonglong2*)(g_Q + (long)(b * Tn + t) * En + h * Dn);
        #pragma unroll
        for (int i = 0; i < 16; i++) {
            ulonglong2 v = qp[i];
            q2[2 * i] = v.x; q2[2 * i + 1] = v.y;
        }
    }

    u64t o2[32];
    #pragma unroll
    for (int i = 0; i < 32; i++) o2[i] = 0ull;
    float m = -1e30f, l = 0.f;
    const int mtype = g_mask_type;

    #pragma unroll 1
    for (int s0 = 0; s0 < Sn; s0 += 64) {
        // pack this thread's 64 mask flags into bits (no smem involved)
        unsigned long long mb = 0ull;
        long mbase = (long)b * Tn * Sn + (long)t * Sn + s0;
        if (mtype == 2) {
            const unsigned long long* mp =
                (const unsigned long long*)((const unsigned char*)mask + mbase);
            #pragma unroll
            for (int w = 0; w < 8; w++) {
                unsigned long long v = mp[w];
                #pragma unroll
                for (int k = 0; k < 8; k++)
                    if ((v >> (8 * k)) & 0xffull) mb |= 1ull << (w * 8 + k);
            }
        } else {
            const int4* mp = (const int4*)((const int*)mask + mbase);
            #pragma unroll
            for (int w = 0; w < 16; w++) {
                int4 v = mp[w];
                if (v.x) mb |= 1ull << (w * 4 + 0);
                if (v.y) mb |= 1ull << (w * 4 + 1);
                if (v.z) mb |= 1ull << (w * 4 + 2);
                if (v.w) mb |= 1ull << (w * 4 + 3);
            }
        }

        __syncthreads();
        // cooperative K/V tile load: 1024 x 16B each, 16 per thread
        #pragma unroll
        for (int p = 0; p < 16; p++) {
            int idx = p * 64 + lane;
            int row = idx >> 4;
            int col = idx & 15;
            long g = (long)(b * Sn + s0 + row) * En + h * Dn;
            Ks[row][col] = ((const ulonglong2*)(g_K + g))[col];
            Vs[row][col] = ((const ulonglong2*)(g_V + g))[col];
        }
        __syncthreads();

        #pragma unroll 2
        for (int j = 0; j < 64; j++) {
            // QK^T dot over 64 dims: 32 packed FMA2 on two accumulators
            u64t acc_a = 0ull, acc_b = 0ull;
            #pragma unroll
            for (int i = 0; i < 16; i++) {
                ulonglong2 kv = Ks[j][i];
                acc_a = fma2(q2[2 * i],     kv.x, acc_a);
                acc_b = fma2(q2[2 * i + 1], kv.y, acc_b);
            }
            float2 ua = unpack2(acc_a);
            float2 ub = unpack2(acc_b);
            float s = (ua.x + ua.y) + (ub.x + ub.y);
            if ((mb >> j) & 1ull) s = -1e9f;

            float mn = fmaxf(m, s);
            if (mn > m) {
                float corr = __expf(m - mn);
                l *= corr;
                u64t c2 = pack2(corr, corr);
                #pragma unroll
                for (int i = 0; i < 32; i++) o2[i] = mul2(o2[i], c2);
                m = mn;
            }
            float p = __expf(s - m);
            l += p;
            u64t p2 = pack2(p, p);
            #pragma unroll
            for (int i = 0; i < 16; i++) {
                ulonglong2 vv = Vs[j][i];
                o2[2 * i]     = fma2(p2, vv.x, o2[2 * i]);
                o2[2 * i + 1] = fma2(p2, vv.y, o2[2 * i + 1]);
            }
        }
    }

    float inv = 1.f / l;
    float4* op = (float4*)(g_Q + (long)(b * Tn + t) * En + h * Dn);
    #pragma unroll
    for (int i = 0; i < 16; i++) {
        float2 a = unpack2(o2[2 * i]);
        float2 c = unpack2(o2[2 * i + 1]);
        op[i] = make_float4(a.x * inv, a.y * inv, c.x * inv, c.y * inv);
    }
}

// ---------------- launch -----------------------------------------------------
// Host body: six plain kernel launches, no CUDA API calls, no __device__
// symbol references. (Resubmission of the untested f32x2 experiment —
// R10 hit a broker capacity timeout before any compile/run.)
extern "C" void kernel_launch(void* const* d_in, const int* in_sizes, int n_in,
                              void* d_out, int out_size) {
    const float* x       = (const float*)d_in[0];   // [B,T,C]
    const float* context = (const float*)d_in[1];   // [B,S,E]
    const void*  pmask   = d_in[2];                 // [B,T,S] (dtype detected)
    const float* w_in    = (const float*)d_in[3];   // [E,C]
    const float* b_in    = (const float*)d_in[4];   // [E]
    const float* wq      = (const float*)d_in[5];   // [E,E]
    const float* bq      = (const float*)d_in[6];
    const float* wk      = (const float*)d_in[7];
    const float* bk      = (const float*)d_in[8];
    const float* wv      = (const float*)d_in[9];
    const float* bv      = (const float*)d_in[10];
    const float* w_out   = (const float*)d_in[11];  // [C,E]
    const float* b_out   = (const float*)d_in[12];  // [C]
    float* out = (float*)d_out;

    detect_mask_kernel<<<1, 256>>>(pmask, in_sizes[2]);
    combine_weights_kernel<<<En, Cn>>>(wq, w_in, b_in, bq);

    // Q = SCALE * (x @ Wc^T + bc) -> g_Q   [8192,512], K=256
    {
        dim3 g(En / 64, (Bn * Tn) / 64);
        gemm_nt_bias<0><<<g, 256>>>(x, nullptr, nullptr, nullptr,
                                    Bn * Tn, En, Cn, SCALE_F);
    }
    // K/V = context @ w^T + b -> g_K / g_V   [8192,512], K=512
    {
        dim3 g(En / 64, (Bn * Sn) / 64);
        gemm_nt_bias<1><<<g, 256>>>(context, wk, bk, nullptr,
                                    Bn * Sn, En, En, 1.f);
        gemm_nt_bias<2><<<g, 256>>>(context, wv, bv, nullptr,
                                    Bn * Sn, En, En, 1.f);
    }
    // attention (in place over g_Q)
    {
        dim3 g(Tn / 64, Bn * Hn);
        attn_kernel<<<g, 64>>>(pmask);
    }
    // out = O @ w_out^T + b_out   [8192,256], K=512
    {
        dim3 g(Cn / 64, (Bn * Tn) / 64);
        gemm_nt_bias<3><<<g, 256>>>(nullptr, w_out, b_out, out,
                                    Bn * Tn, Cn, En, 1.f);
    }
}

// round 12
// speedup vs baseline: 1.6062x; 1.5068x over previous
#include <cuda_runtime.h>

// Problem constants
#define Bn 4
#define Tn 2048
#define Sn 2048
#define Cn 256
#define En 512
#define Hn 8
#define Dn 64
#define SCALE_F 0.04419417382415922f   // 512^-0.5

// ---------------- scratch (static device globals; no allocations) ----------
__device__ float g_Q[Bn * Tn * En];     // pre-scaled Q, then attention out
__device__ float g_K[Bn * Sn * En];     // [B*S, E]
__device__ float g_V[Bn * Sn * En];     // [B*S, E]
__device__ float g_Wc[En * Cn];         // wq @ w_in
__device__ float g_bc[En];              // bq + wq @ b_in
__device__ int   g_mask_type;           // 0=int32 words, 1=float32 words, 2=bytes

// ---------------- mask dtype detection -------------------------------------
__global__ void detect_mask_kernel(const void* __restrict__ mask, int nelem) {
    __shared__ int s_notint, s_notfloat;
    if (threadIdx.x == 0) { s_notint = 0; s_notfloat = 0; }
    __syncthreads();
    int n = nelem < 4096 ? nelem : 4096;
    const unsigned int* w = (const unsigned int*)mask;
    int ni = 0, nf = 0;
    for (int i = threadIdx.x; i < n; i += blockDim.x) {
        unsigned int v = w[i];
        if (v > 1u) ni = 1;
        if (v != 0u && v != 0x3F800000u) nf = 1;
    }
    if (ni) atomicOr(&s_notint, 1);
    if (nf) atomicOr(&s_notfloat, 1);
    __syncthreads();
    if (threadIdx.x == 0)
        g_mask_type = (s_notint == 0) ? 0 : (s_notfloat == 0 ? 1 : 2);
}

// ---------------- fold wq @ w_in -------------------------------------------
__global__ void combine_weights_kernel(const float* __restrict__ wq,
                                       const float* __restrict__ w_in,
                                       const float* __restrict__ b_in,
                                       const float* __restrict__ bq) {
    int e = blockIdx.x;      // 0..E-1
    int c = threadIdx.x;     // 0..C-1
    float acc = 0.f;
    #pragma unroll 4
    for (int j = 0; j < En; j++)
        acc = fmaf(wq[e * En + j], w_in[j * Cn + c], acc);
    g_Wc[e * Cn + c] = acc;
    if (c == 0) {
        float a = bq[e];
        for (int j = 0; j < En; j++)
            a = fmaf(wq[e * En + j], b_in[j], a);
        g_bc[e] = a;
    }
}

// ---------------- tiled NT GEMM with bias -----------------------------------
// C[m,n] = alpha * ( sum_k A[m,k]*B[n,k] + bias[n] )
//   MODE 0: A=param(x),       B=g_Wc,  bias=g_bc,  C=g_Q,  alpha=SCALE
//   MODE 1: A=param(context), B=param, bias=param, C=g_K
//   MODE 2: A=param(context), B=param, bias=param, C=g_V
//   MODE 3: A=g_Q (attn out), B=param, bias=param, C=param(out)
template<int MODE>
__global__ __launch_bounds__(256)
void gemm_nt_bias(const float* __restrict__ A_in, const float* __restrict__ B_in,
                  const float* __restrict__ bias_in, float* __restrict__ C_out,
                  int M, int N, int K, float alpha) {
    const float* A    = (MODE == 3) ? (const float*)g_Q : A_in;
    const float* B    = (MODE == 0) ? (const float*)g_Wc : B_in;
    const float* bias = (MODE == 0) ? (const float*)g_bc : bias_in;
    float* C;
    if      (MODE == 0) C = g_Q;
    else if (MODE == 1) C = g_K;
    else if (MODE == 2) C = g_V;
    else                C = C_out;

    const int BM = 64, BN = 64, BK = 16;
    __shared__ float As[BK][BM];
    __shared__ float Bs[BK][BN];
    int tid = threadIdx.x;
    int tx = tid & 15;
    int ty = tid >> 4;
    int bm = blockIdx.y * BM;
    int bn = blockIdx.x * BN;
    int la_row = tid >> 2;
    int la_col = (tid & 3) * 4;

    float acc[4][4] = {};
    const float* Ap = A + (long)(bm + la_row) * K + la_col;
    const float* Bp = B + (long)(bn + la_row) * K + la_col;

    for (int k0 = 0; k0 < K; k0 += BK) {
        float4 av = *(const float4*)(Ap + k0);
        float4 bv = *(const float4*)(Bp + k0);
        As[la_col + 0][la_row] = av.x; As[la_col + 1][la_row] = av.y;
        As[la_col + 2][la_row] = av.z; As[la_col + 3][la_row] = av.w;
        Bs[la_col + 0][la_row] = bv.x; Bs[la_col + 1][la_row] = bv.y;
        Bs[la_col + 2][la_row] = bv.z; Bs[la_col + 3][la_row] = bv.w;
        __syncthreads();
        #pragma unroll
        for (int kk = 0; kk < BK; kk++) {
            float4 a4 = *(const float4*)&As[kk][ty * 4];
            float4 b4 = *(const float4*)&Bs[kk][tx * 4];
            float a[4] = {a4.x, a4.y, a4.z, a4.w};
            float b[4] = {b4.x, b4.y, b4.z, b4.w};
            #pragma unroll
            for (int i = 0; i < 4; i++)
                #pragma unroll
                for (int j = 0; j < 4; j++)
                    acc[i][j] = fmaf(a[i], b[j], acc[i][j]);
        }
        __syncthreads();
    }
    float bb[4];
    #pragma unroll
    for (int j = 0; j < 4; j++) bb[j] = bias[bn + tx * 4 + j];
    #pragma unroll
    for (int i = 0; i < 4; i++) {
        float4 r;
        r.x = alpha * (acc[i][0] + bb[0]);
        r.y = alpha * (acc[i][1] + bb[1]);
        r.z = alpha * (acc[i][2] + bb[2]);
        r.w = alpha * (acc[i][3] + bb[3]);
        *(float4*)&C[(long)(bm + ty * 4 + i) * N + bn + tx * 4] = r;
    }
}

// ---------------- tf32 warp-MMA helper --------------------------------------
// D += A * B, m16n8k8, tf32 inputs (raw fp32 bits; HW truncates mantissa).
__device__ __forceinline__ void mma_tf32(float& d0, float& d1, float& d2, float& d3,
                                         float a0, float a1, float a2, float a3,
                                         float b0, float b1) {
    unsigned ua0 = __float_as_uint(a0), ua1 = __float_as_uint(a1);
    unsigned ua2 = __float_as_uint(a2), ua3 = __float_as_uint(a3);
    unsigned ub0 = __float_as_uint(b0), ub1 = __float_as_uint(b1);
    asm volatile(
        "mma.sync.aligned.m16n8k8.row.col.f32.tf32.tf32.f32 "
        "{%0,%1,%2,%3}, {%4,%5,%6,%7}, {%8,%9}, {%0,%1,%2,%3};"
        : "+f"(d0), "+f"(d1), "+f"(d2), "+f"(d3)
        : "r"(ua0), "r"(ua1), "r"(ua2), "r"(ua3), "r"(ub0), "r"(ub1));
}

// ---------------- flash attention via tensor-core MMA -----------------------
// grid: (T/64, B*H), block: 128 threads (4 warps). Warp w owns q-rows
// [16w, 16w+16) of the block's 64-row q-tile. Flash loop over 64-key tiles.
// Fragment layouts (PTX m16n8k8): grp = lane>>2, t4 = lane&3.
//   A:  a0(grp,t4) a1(grp+8,t4) a2(grp,t4+4) a3(grp+8,t4+4)
//   B:  b0(t4,grp) b1(t4+4,grp)      (col-major k x n)
//   C:  c0(grp,2t4) c1(grp,2t4+1) c2(grp+8,2t4) c3(grp+8,2t4+1)
__global__ __launch_bounds__(128)
void attn_mma_kernel(const void* __restrict__ mask) {
    extern __shared__ float smem[];
    const int bh = blockIdx.y;
    const int b = bh / Hn, h = bh % Hn;
    const int qbase = blockIdx.x * 64;
    const int tid = threadIdx.x;
    const int warp = tid >> 5;
    const int lane = tid & 31;
    const int grp = lane >> 2;
    const int t4 = lane & 3;

    // smem layout (floats): Ks[64][68] | Vt[64][68] | Pw[4][16][68] | mrow u64[64]
    float (*Ks)[68] = (float(*)[68])smem;
    float (*Vt)[68] = (float(*)[68])(smem + 64 * 68);
    float (*Pw)[68] = (float(*)[68])(smem + 2 * 64 * 68 + warp * 16 * 68);
    unsigned long long* mrow = (unsigned long long*)(smem + 3 * 64 * 68);

    // Q A-fragments for this warp's 16 rows (pre-scaled by SCALE in projection)
    const float* Qp = g_Q + (long)(b * Tn + qbase + warp * 16) * En + h * Dn;
    float qf[8][4];
    #pragma unroll
    for (int ks = 0; ks < 8; ks++) {
        qf[ks][0] = Qp[(long)grp * En + 8 * ks + t4];
        qf[ks][1] = Qp[(long)(grp + 8) * En + 8 * ks + t4];
        qf[ks][2] = Qp[(long)grp * En + 8 * ks + t4 + 4];
        qf[ks][3] = Qp[(long)(grp + 8) * En + 8 * ks + t4 + 4];
    }

    float o[8][4];
    #pragma unroll
    for (int nt = 0; nt < 8; nt++)
        o[nt][0] = o[nt][1] = o[nt][2] = o[nt][3] = 0.f;
    float m0 = -1e30f, m1 = -1e30f, l0 = 0.f, l1 = 0.f;
    const int mtype = g_mask_type;

    #pragma unroll 1
    for (int s0 = 0; s0 < Sn; s0 += 64) {
        __syncthreads();   // protect Ks/Vt/mrow from overwrite while in use

        // cooperative K/V tile load: thread -> (row = tid/2, cols half)
        {
            int row = tid >> 1;
            int c0 = (tid & 1) * 32;
            long gbase = (long)(b * Sn + s0 + row) * En + h * Dn + c0;
            const float4* kg = (const float4*)(g_K + gbase);
            const float4* vg = (const float4*)(g_V + gbase);
            #pragma unroll
            for (int i = 0; i < 8; i++) {
                float4 kv = kg[i];
                *(float4*)&Ks[row][c0 + 4 * i] = kv;
                float4 vv = vg[i];
                int d = c0 + 4 * i;
                Vt[d + 0][row] = vv.x;
                Vt[d + 1][row] = vv.y;
                Vt[d + 2][row] = vv.z;
                Vt[d + 3][row] = vv.w;
            }
        }
        // mask pack: threads 0..63, one row each -> 64-bit mask
        if (tid < 64) {
            unsigned long long mb = 0ull;
            long mbase = (long)b * Tn * Sn + (long)(qbase + tid) * Sn + s0;
            if (mtype == 2) {
                const unsigned long long* mp =
                    (const unsigned long long*)((const unsigned char*)mask + mbase);
                #pragma unroll
                for (int w = 0; w < 8; w++) {
                    unsigned long long v = mp[w];
                    #pragma unroll
                    for (int k = 0; k < 8; k++)
                        if ((v >> (8 * k)) & 0xffull) mb |= 1ull << (w * 8 + k);
                }
            } else {
                const int4* mp = (const int4*)((const int*)mask + mbase);
                #pragma unroll
                for (int w = 0; w < 16; w++) {
                    int4 v = mp[w];
                    if (v.x) mb |= 1ull << (w * 4 + 0);
                    if (v.y) mb |= 1ull << (w * 4 + 1);
                    if (v.z) mb |= 1ull << (w * 4 + 2);
                    if (v.w) mb |= 1ull << (w * 4 + 3);
                }
            }
            mrow[tid] = mb;
        }
        __syncthreads();

        // ---- S = Q K^T for this warp's 16 rows x 64 keys ----
        float sv[8][4];
        #pragma unroll
        for (int nt = 0; nt < 8; nt++) {
            float c0r = 0.f, c1r = 0.f, c2r = 0.f, c3r = 0.f;
            #pragma unroll
            for (int ks = 0; ks < 8; ks++) {
                float b0 = Ks[8 * nt + grp][8 * ks + t4];
                float b1 = Ks[8 * nt + grp][8 * ks + t4 + 4];
                mma_tf32(c0r, c1r, c2r, c3r,
                         qf[ks][0], qf[ks][1], qf[ks][2], qf[ks][3], b0, b1);
            }
            sv[nt][0] = c0r; sv[nt][1] = c1r; sv[nt][2] = c2r; sv[nt][3] = c3r;
        }

        // ---- mask ----
        unsigned long long mr0 = mrow[16 * warp + grp];
        unsigned long long mr1 = mrow[16 * warp + grp + 8];
        #pragma unroll
        for (int nt = 0; nt < 8; nt++) {
            int col = 8 * nt + 2 * t4;
            if ((mr0 >> col) & 1ull)       sv[nt][0] = -1e9f;
            if ((mr0 >> (col + 1)) & 1ull) sv[nt][1] = -1e9f;
            if ((mr1 >> col) & 1ull)       sv[nt][2] = -1e9f;
            if ((mr1 >> (col + 1)) & 1ull) sv[nt][3] = -1e9f;
        }

        // ---- online softmax (rows grp and grp+8) ----
        float tmax0 = -1e30f, tmax1 = -1e30f;
        #pragma unroll
        for (int nt = 0; nt < 8; nt++) {
            tmax0 = fmaxf(tmax0, fmaxf(sv[nt][0], sv[nt][1]));
            tmax1 = fmaxf(tmax1, fmaxf(sv[nt][2], sv[nt][3]));
        }
        tmax0 = fmaxf(tmax0, __shfl_xor_sync(0xffffffffu, tmax0, 1));
        tmax0 = fmaxf(tmax0, __shfl_xor_sync(0xffffffffu, tmax0, 2));
        tmax1 = fmaxf(tmax1, __shfl_xor_sync(0xffffffffu, tmax1, 1));
        tmax1 = fmaxf(tmax1, __shfl_xor_sync(0xffffffffu, tmax1, 2));

        float m0n = fmaxf(m0, tmax0);
        float m1n = fmaxf(m1, tmax1);
        float corr0 = __expf(m0 - m0n);
        float corr1 = __expf(m1 - m1n);
        m0 = m0n; m1 = m1n;

        float lp0 = 0.f, lp1 = 0.f;
        #pragma unroll
        for (int nt = 0; nt < 8; nt++) {
            float p0 = __expf(sv[nt][0] - m0);
            float p1 = __expf(sv[nt][1] - m0);
            float p2 = __expf(sv[nt][2] - m1);
            float p3 = __expf(sv[nt][3] - m1);
            lp0 += p0 + p1; lp1 += p2 + p3;
            sv[nt][0] = p0; sv[nt][1] = p1; sv[nt][2] = p2; sv[nt][3] = p3;
        }
        l0 = l0 * corr0 + lp0;
        l1 = l1 * corr1 + lp1;
        #pragma unroll
        for (int nt = 0; nt < 8; nt++) {
            o[nt][0] *= corr0; o[nt][1] *= corr0;
            o[nt][2] *= corr1; o[nt][3] *= corr1;
        }

        // ---- stage P (C-layout -> smem) ----
        #pragma unroll
        for (int nt = 0; nt < 8; nt++) {
            int col = 8 * nt + 2 * t4;
            *(float2*)&Pw[grp][col]     = make_float2(sv[nt][0], sv[nt][1]);
            *(float2*)&Pw[grp + 8][col] = make_float2(sv[nt][2], sv[nt][3]);
        }
        __syncwarp();

        // ---- O += P V ----
        #pragma unroll
        for (int ks = 0; ks < 8; ks++) {
            float a0 = Pw[grp][8 * ks + t4];
            float a1 = Pw[grp + 8][8 * ks + t4];
            float a2 = Pw[grp][8 * ks + t4 + 4];
            float a3 = Pw[grp + 8][8 * ks + t4 + 4];
            #pragma unroll
            for (int nt = 0; nt < 8; nt++) {
                float b0 = Vt[8 * nt + grp][8 * ks + t4];
                float b1 = Vt[8 * nt + grp][8 * ks + t4 + 4];
                mma_tf32(o[nt][0], o[nt][1], o[nt][2], o[nt][3],
                         a0, a1, a2, a3, b0, b1);
            }
        }
        __syncwarp();   // Pw reads done before next tile's staging
    }

    // final row sums across quad, normalize, write in place over g_Q
    l0 += __shfl_xor_sync(0xffffffffu, l0, 1);
    l0 += __shfl_xor_sync(0xffffffffu, l0, 2);
    l1 += __shfl_xor_sync(0xffffffffu, l1, 1);
    l1 += __shfl_xor_sync(0xffffffffu, l1, 2);
    float inv0 = 1.f / l0;
    float inv1 = 1.f / l1;

    float* Op = g_Q + (long)(b * Tn + qbase + warp * 16) * En + h * Dn;
    #pragma unroll
    for (int nt = 0; nt < 8; nt++) {
        int col = 8 * nt + 2 * t4;
        *(float2*)&Op[(long)grp * En + col] =
            make_float2(o[nt][0] * inv0, o[nt][1] * inv0);
        *(float2*)&Op[(long)(grp + 8) * En + col] =
            make_float2(o[nt][2] * inv1, o[nt][3] * inv1);
    }
}

// ---------------- launch -----------------------------------------------------
extern "C" void kernel_launch(void* const* d_in, const int* in_sizes, int n_in,
                              void* d_out, int out_size) {
    const float* x       = (const float*)d_in[0];   // [B,T,C]
    const float* context = (const float*)d_in[1];   // [B,S,E]
    const void*  pmask   = d_in[2];                 // [B,T,S] (dtype detected)
    const float* w_in    = (const float*)d_in[3];   // [E,C]
    const float* b_in    = (const float*)d_in[4];   // [E]
    const float* wq      = (const float*)d_in[5];   // [E,E]
    const float* bq      = (const float*)d_in[6];
    const float* wk      = (const float*)d_in[7];
    const float* bk      = (const float*)d_in[8];
    const float* wv      = (const float*)d_in[9];
    const float* bv      = (const float*)d_in[10];
    const float* w_out   = (const float*)d_in[11];  // [C,E]
    const float* b_out   = (const float*)d_in[12];  // [C]
    float* out = (float*)d_out;

    detect_mask_kernel<<<1, 256>>>(pmask, in_sizes[2]);
    combine_weights_kernel<<<En, Cn>>>(wq, w_in, b_in, bq);

    // Q = SCALE * (x @ Wc^T + bc) -> g_Q   [8192,512], K=256
    {
        dim3 g(En / 64, (Bn * Tn) / 64);
        gemm_nt_bias<0><<<g, 256>>>(x, nullptr, nullptr, nullptr,
                                    Bn * Tn, En, Cn, SCALE_F);
    }
    // K/V = context @ w^T + b -> g_K / g_V   [8192,512], K=512
    {
        dim3 g(En / 64, (Bn * Sn) / 64);
        gemm_nt_bias<1><<<g, 256>>>(context, wk, bk, nullptr,
                                    Bn * Sn, En, En, 1.f);
        gemm_nt_bias<2><<<g, 256>>>(context, wv, bv, nullptr,
                                    Bn * Sn, En, En, 1.f);
    }
    // attention (tensor-core MMA, in place over g_Q)
    {
        const int smem_bytes = (3 * 64 * 68) * 4 + 64 * 8;   // 52736
        cudaFuncSetAttribute(attn_mma_kernel,
                             cudaFuncAttributeMaxDynamicSharedMemorySize,
                             smem_bytes);
        dim3 g(Tn / 64, Bn * Hn);
        attn_mma_kernel<<<g, 128, smem_bytes>>>(pmask);
    }
    // out = O @ w_out^T + b_out   [8192,256], K=512
    {
        dim3 g(Cn / 64, (Bn * Tn) / 64);
        gemm_nt_bias<3><<<g, 256>>>(nullptr, w_out, b_out, out,
                                    Bn * Tn, Cn, En, 1.f);
    }
}

// round 13
// speedup vs baseline: 1.6828x; 1.0477x over previous
#include <cuda_runtime.h>

// Problem constants
#define Bn 4
#define Tn 2048
#define Sn 2048
#define Cn 256
#define En 512
#define Hn 8
#define Dn 64
#define SCALE_F 0.04419417382415922f   // 512^-0.5

#define KPITCH 68
#define VPITCH 72

// ---------------- scratch (static device globals; no allocations) ----------
__device__ float g_Q[Bn * Tn * En];     // pre-scaled Q, then attention out
__device__ float g_K[Bn * Sn * En];     // [B*S, E]
__device__ float g_V[Bn * Sn * En];     // [B*S, E]
__device__ float g_Wc[En * Cn];         // wq @ w_in
__device__ float g_bc[En];              // bq + wq @ b_in
__device__ int   g_mask_type;           // 0=int32 words, 1=float32 words, 2=bytes

// ---------------- mask dtype detection -------------------------------------
__global__ void detect_mask_kernel(const void* __restrict__ mask, int nelem) {
    __shared__ int s_notint, s_notfloat;
    if (threadIdx.x == 0) { s_notint = 0; s_notfloat = 0; }
    __syncthreads();
    int n = nelem < 4096 ? nelem : 4096;
    const unsigned int* w = (const unsigned int*)mask;
    int ni = 0, nf = 0;
    for (int i = threadIdx.x; i < n; i += blockDim.x) {
        unsigned int v = w[i];
        if (v > 1u) ni = 1;
        if (v != 0u && v != 0x3F800000u) nf = 1;
    }
    if (ni) atomicOr(&s_notint, 1);
    if (nf) atomicOr(&s_notfloat, 1);
    __syncthreads();
    if (threadIdx.x == 0)
        g_mask_type = (s_notint == 0) ? 0 : (s_notfloat == 0 ? 1 : 2);
}

// ---------------- fold wq @ w_in -------------------------------------------
__global__ void combine_weights_kernel(const float* __restrict__ wq,
                                       const float* __restrict__ w_in,
                                       const float* __restrict__ b_in,
                                       const float* __restrict__ bq) {
    int e = blockIdx.x;
    int c = threadIdx.x;
    float acc = 0.f;
    #pragma unroll 4
    for (int j = 0; j < En; j++)
        acc = fmaf(wq[e * En + j], w_in[j * Cn + c], acc);
    g_Wc[e * Cn + c] = acc;
    if (c == 0) {
        float a = bq[e];
        for (int j = 0; j < En; j++)
            a = fmaf(wq[e * En + j], b_in[j], a);
        g_bc[e] = a;
    }
}

// ---------------- tiled NT GEMM with bias -----------------------------------
template<int MODE>
__global__ __launch_bounds__(256)
void gemm_nt_bias(const float* __restrict__ A_in, const float* __restrict__ B_in,
                  const float* __restrict__ bias_in, float* __restrict__ C_out,
                  int M, int N, int K, float alpha) {
    const float* A    = (MODE == 3) ? (const float*)g_Q : A_in;
    const float* B    = (MODE == 0) ? (const float*)g_Wc : B_in;
    const float* bias = (MODE == 0) ? (const float*)g_bc : bias_in;
    float* C;
    if      (MODE == 0) C = g_Q;
    else if (MODE == 1) C = g_K;
    else if (MODE == 2) C = g_V;
    else                C = C_out;

    const int BM = 64, BN = 64, BK = 16;
    __shared__ float As[BK][BM];
    __shared__ float Bs[BK][BN];
    int tid = threadIdx.x;
    int tx = tid & 15;
    int ty = tid >> 4;
    int bm = blockIdx.y * BM;
    int bn = blockIdx.x * BN;
    int la_row = tid >> 2;
    int la_col = (tid & 3) * 4;

    float acc[4][4] = {};
    const float* Ap = A + (long)(bm + la_row) * K + la_col;
    const float* Bp = B + (long)(bn + la_row) * K + la_col;

    for (int k0 = 0; k0 < K; k0 += BK) {
        float4 av = *(const float4*)(Ap + k0);
        float4 bv = *(const float4*)(Bp + k0);
        As[la_col + 0][la_row] = av.x; As[la_col + 1][la_row] = av.y;
        As[la_col + 2][la_row] = av.z; As[la_col + 3][la_row] = av.w;
        Bs[la_col + 0][la_row] = bv.x; Bs[la_col + 1][la_row] = bv.y;
        Bs[la_col + 2][la_row] = bv.z; Bs[la_col + 3][la_row] = bv.w;
        __syncthreads();
        #pragma unroll
        for (int kk = 0; kk < BK; kk++) {
            float4 a4 = *(const float4*)&As[kk][ty * 4];
            float4 b4 = *(const float4*)&Bs[kk][tx * 4];
            float a[4] = {a4.x, a4.y, a4.z, a4.w};
            float b[4] = {b4.x, b4.y, b4.z, b4.w};
            #pragma unroll
            for (int i = 0; i < 4; i++)
                #pragma unroll
                for (int j = 0; j < 4; j++)
                    acc[i][j] = fmaf(a[i], b[j], acc[i][j]);
        }
        __syncthreads();
    }
    float bb[4];
    #pragma unroll
    for (int j = 0; j < 4; j++) bb[j] = bias[bn + tx * 4 + j];
    #pragma unroll
    for (int i = 0; i < 4; i++) {
        float4 r;
        r.x = alpha * (acc[i][0] + bb[0]);
        r.y = alpha * (acc[i][1] + bb[1]);
        r.z = alpha * (acc[i][2] + bb[2]);
        r.w = alpha * (acc[i][3] + bb[3]);
        *(float4*)&C[(long)(bm + ty * 4 + i) * N + bn + tx * 4] = r;
    }
}

// ---------------- tf32 warp-MMA helper --------------------------------------
__device__ __forceinline__ void mma_tf32(float& d0, float& d1, float& d2, float& d3,
                                         float a0, float a1, float a2, float a3,
                                         float b0, float b1) {
    unsigned ua0 = __float_as_uint(a0), ua1 = __float_as_uint(a1);
    unsigned ua2 = __float_as_uint(a2), ua3 = __float_as_uint(a3);
    unsigned ub0 = __float_as_uint(b0), ub1 = __float_as_uint(b1);
    asm volatile(
        "mma.sync.aligned.m16n8k8.row.col.f32.tf32.tf32.f32 "
        "{%0,%1,%2,%3}, {%4,%5,%6,%7}, {%8,%9}, {%0,%1,%2,%3};"
        : "+f"(d0), "+f"(d1), "+f"(d2), "+f"(d3)
        : "r"(ua0), "r"(ua1), "r"(ua2), "r"(ua3), "r"(ub0), "r"(ub1));
}

__device__ __forceinline__ void cpasync16(unsigned smem_addr, const void* gptr) {
    asm volatile("cp.async.cg.shared.global [%0], [%1], 16;"
                 :: "r"(smem_addr), "l"(gptr));
}
__device__ __forceinline__ void cpasync_commit() {
    asm volatile("cp.async.commit_group;");
}
__device__ __forceinline__ void cpasync_wait0() {
    asm volatile("cp.async.wait_group 0;" ::: "memory");
}

// ---------------- flash attention via tensor-core MMA + cp.async ------------
// grid: (T/64, B*H), block: 128 threads (4 warps). Warp w owns q-rows
// [16w,16w+16). Double-buffered K/V tiles via cp.async; V untransposed
// (pitch 72 => conflict-free PV B-fragment reads); mask packed in registers
// and distributed via shfl.
__global__ __launch_bounds__(128)
void attn_mma_kernel(const void* __restrict__ mask) {
    extern __shared__ float smem[];
    // layout: Ks[2][64][KPITCH] | Vs[2][64][VPITCH] | Pw[4][16][KPITCH]
    float (*Ks)[64][KPITCH] = (float(*)[64][KPITCH])smem;
    float (*Vs)[64][VPITCH] = (float(*)[64][VPITCH])(smem + 2 * 64 * KPITCH);
    float (*Pw)[KPITCH] = (float(*)[KPITCH])
        (smem + 2 * 64 * KPITCH + 2 * 64 * VPITCH + (threadIdx.x >> 5) * 16 * KPITCH);

    const int bh = blockIdx.y;
    const int b = bh / Hn, h = bh % Hn;
    const int qbase = blockIdx.x * 64;
    const int tid = threadIdx.x;
    const int warp = tid >> 5;
    const int lane = tid & 31;
    const int grp = lane >> 2;
    const int t4 = lane & 3;
    const int mtype = g_mask_type;

    unsigned sb;
    asm("{ .reg .u64 t; cvta.to.shared.u64 t, %1; cvt.u32.u64 %0, t; }"
        : "=r"(sb) : "l"(smem));
    const unsigned ks_u32 = sb;
    const unsigned vs_u32 = sb + 2 * 64 * KPITCH * 4;

    // Q A-fragments for this warp's 16 rows (pre-scaled by SCALE)
    const float* Qp = g_Q + (long)(b * Tn + qbase + warp * 16) * En + h * Dn;
    float qf[8][4];
    #pragma unroll
    for (int ks = 0; ks < 8; ks++) {
        qf[ks][0] = Qp[(long)grp * En + 8 * ks + t4];
        qf[ks][1] = Qp[(long)(grp + 8) * En + 8 * ks + t4];
        qf[ks][2] = Qp[(long)grp * En + 8 * ks + t4 + 4];
        qf[ks][3] = Qp[(long)(grp + 8) * En + 8 * ks + t4 + 4];
    }

    // copy geometry: thread -> row = tid/2, 32-col half = (tid&1)*32, 8x16B each
    const int crow = tid >> 1;
    const int ccol = (tid & 1) * 32;
    const float* Kg = g_K + (long)(b * Sn + crow) * En + h * Dn + ccol;
    const float* Vg = g_V + (long)(b * Sn + crow) * En + h * Dn + ccol;
    const unsigned kdst = ks_u32 + (crow * KPITCH + ccol) * 4;
    const unsigned vdst = vs_u32 + (crow * VPITCH + ccol) * 4;
    const unsigned kbufstride = 64 * KPITCH * 4;
    const unsigned vbufstride = 64 * VPITCH * 4;

    auto prefetch = [&](int buf, int s0) {
        const float* kg = Kg + (long)s0 * En;
        const float* vg = Vg + (long)s0 * En;
        unsigned kd = kdst + buf * kbufstride;
        unsigned vd = vdst + buf * vbufstride;
        #pragma unroll
        for (int i = 0; i < 8; i++) {
            cpasync16(kd + 16 * i, kg + 4 * i);
            cpasync16(vd + 16 * i, vg + 4 * i);
        }
        cpasync_commit();
    };

    float o[8][4];
    #pragma unroll
    for (int nt = 0; nt < 8; nt++)
        o[nt][0] = o[nt][1] = o[nt][2] = o[nt][3] = 0.f;
    float m0 = -1e30f, m1 = -1e30f, l0 = 0.f, l1 = 0.f;

    int cur = 0;
    prefetch(0, 0);

    #pragma unroll 1
    for (int it = 0; it < Sn / 64; ++it) {
        const int s0 = it * 64;
        cpasync_wait0();
        __syncthreads();
        if (it + 1 < Sn / 64) prefetch(cur ^ 1, s0 + 64);

        // ---- mask pack in registers: lane l<16 packs row qbase+16*warp+l ----
        unsigned long long mypack = 0ull;
        if (lane < 16) {
            long mbase = (long)b * Tn * Sn + (long)(qbase + 16 * warp + lane) * Sn + s0;
            if (mtype == 2) {
                const unsigned long long* mp =
                    (const unsigned long long*)((const unsigned char*)mask + mbase);
                #pragma unroll
                for (int w = 0; w < 8; w++) {
                    unsigned long long v = mp[w];
                    #pragma unroll
                    for (int k = 0; k < 8; k++)
                        if ((v >> (8 * k)) & 0xffull) mypack |= 1ull << (w * 8 + k);
                }
            } else {
                const int4* mp = (const int4*)((const int*)mask + mbase);
                #pragma unroll
                for (int w = 0; w < 16; w++) {
                    int4 v = mp[w];
                    if (v.x) mypack |= 1ull << (w * 4 + 0);
                    if (v.y) mypack |= 1ull << (w * 4 + 1);
                    if (v.z) mypack |= 1ull << (w * 4 + 2);
                    if (v.w) mypack |= 1ull << (w * 4 + 3);
                }
            }
        }
        unsigned long long mr0 = __shfl_sync(0xffffffffu, mypack, grp);
        unsigned long long mr1 = __shfl_sync(0xffffffffu, mypack, grp + 8);

        // ---- S = Q K^T ----
        float sv[8][4];
        #pragma unroll
        for (int nt = 0; nt < 8; nt++) {
            float c0r = 0.f, c1r = 0.f, c2r = 0.f, c3r = 0.f;
            #pragma unroll
            for (int ks = 0; ks < 8; ks++) {
                float b0 = Ks[cur][8 * nt + grp][8 * ks + t4];
                float b1 = Ks[cur][8 * nt + grp][8 * ks + t4 + 4];
                mma_tf32(c0r, c1r, c2r, c3r,
                         qf[ks][0], qf[ks][1], qf[ks][2], qf[ks][3], b0, b1);
            }
            sv[nt][0] = c0r; sv[nt][1] = c1r; sv[nt][2] = c2r; sv[nt][3] = c3r;
        }

        // ---- mask ----
        #pragma unroll
        for (int nt = 0; nt < 8; nt++) {
            int col = 8 * nt + 2 * t4;
            if ((mr0 >> col) & 1ull)       sv[nt][0] = -1e9f;
            if ((mr0 >> (col + 1)) & 1ull) sv[nt][1] = -1e9f;
            if ((mr1 >> col) & 1ull)       sv[nt][2] = -1e9f;
            if ((mr1 >> (col + 1)) & 1ull) sv[nt][3] = -1e9f;
        }

        // ---- online softmax ----
        float tmax0 = -1e30f, tmax1 = -1e30f;
        #pragma unroll
        for (int nt = 0; nt < 8; nt++) {
            tmax0 = fmaxf(tmax0, fmaxf(sv[nt][0], sv[nt][1]));
            tmax1 = fmaxf(tmax1, fmaxf(sv[nt][2], sv[nt][3]));
        }
        tmax0 = fmaxf(tmax0, __shfl_xor_sync(0xffffffffu, tmax0, 1));
        tmax0 = fmaxf(tmax0, __shfl_xor_sync(0xffffffffu, tmax0, 2));
        tmax1 = fmaxf(tmax1, __shfl_xor_sync(0xffffffffu, tmax1, 1));
        tmax1 = fmaxf(tmax1, __shfl_xor_sync(0xffffffffu, tmax1, 2));

        float m0n = fmaxf(m0, tmax0);
        float m1n = fmaxf(m1, tmax1);
        float corr0 = __expf(m0 - m0n);
        float corr1 = __expf(m1 - m1n);
        m0 = m0n; m1 = m1n;

        float lp0 = 0.f, lp1 = 0.f;
        #pragma unroll
        for (int nt = 0; nt < 8; nt++) {
            float p0 = __expf(sv[nt][0] - m0);
            float p1 = __expf(sv[nt][1] - m0);
            float p2 = __expf(sv[nt][2] - m1);
            float p3 = __expf(sv[nt][3] - m1);
            lp0 += p0 + p1; lp1 += p2 + p3;
            sv[nt][0] = p0; sv[nt][1] = p1; sv[nt][2] = p2; sv[nt][3] = p3;
        }
        l0 = l0 * corr0 + lp0;
        l1 = l1 * corr1 + lp1;
        #pragma unroll
        for (int nt = 0; nt < 8; nt++) {
            o[nt][0] *= corr0; o[nt][1] *= corr0;
            o[nt][2] *= corr1; o[nt][3] *= corr1;
        }

        // ---- stage P (C-layout -> per-warp smem) ----
        #pragma unroll
        for (int nt = 0; nt < 8; nt++) {
            int col = 8 * nt + 2 * t4;
            *(float2*)&Pw[grp][col]     = make_float2(sv[nt][0], sv[nt][1]);
            *(float2*)&Pw[grp + 8][col] = make_float2(sv[nt][2], sv[nt][3]);
        }
        __syncwarp();

        // ---- O += P V  (V untransposed: B[k=key][n=d] at Vs[8ks+t4][8nt+grp]) ----
        #pragma unroll
        for (int ks = 0; ks < 8; ks++) {
            float a0 = Pw[grp][8 * ks + t4];
            float a1 = Pw[grp + 8][8 * ks + t4];
            float a2 = Pw[grp][8 * ks + t4 + 4];
            float a3 = Pw[grp + 8][8 * ks + t4 + 4];
            #pragma unroll
            for (int nt = 0; nt < 8; nt++) {
                float b0 = Vs[cur][8 * ks + t4][8 * nt + grp];
                float b1 = Vs[cur][8 * ks + t4 + 4][8 * nt + grp];
                mma_tf32(o[nt][0], o[nt][1], o[nt][2], o[nt][3],
                         a0, a1, a2, a3, b0, b1);
            }
        }
        __syncwarp();
        cur ^= 1;
    }

    // final normalize + in-place write over g_Q
    l0 += __shfl_xor_sync(0xffffffffu, l0, 1);
    l0 += __shfl_xor_sync(0xffffffffu, l0, 2);
    l1 += __shfl_xor_sync(0xffffffffu, l1, 1);
    l1 += __shfl_xor_sync(0xffffffffu, l1, 2);
    float inv0 = 1.f / l0;
    float inv1 = 1.f / l1;

    float* Op = g_Q + (long)(b * Tn + qbase + warp * 16) * En + h * Dn;
    #pragma unroll
    for (int nt = 0; nt < 8; nt++) {
        int col = 8 * nt + 2 * t4;
        *(float2*)&Op[(long)grp * En + col] =
            make_float2(o[nt][0] * inv0, o[nt][1] * inv0);
        *(float2*)&Op[(long)(grp + 8) * En + col] =
            make_float2(o[nt][2] * inv1, o[nt][3] * inv1);
    }
}

// ---------------- launch -----------------------------------------------------
extern "C" void kernel_launch(void* const* d_in, const int* in_sizes, int n_in,
                              void* d_out, int out_size) {
    const float* x       = (const float*)d_in[0];
    const float* context = (const float*)d_in[1];
    const void*  pmask   = d_in[2];
    const float* w_in    = (const float*)d_in[3];
    const float* b_in    = (const float*)d_in[4];
    const float* wq      = (const float*)d_in[5];
    const float* bq      = (const float*)d_in[6];
    const float* wk      = (const float*)d_in[7];
    const float* bk      = (const float*)d_in[8];
    const float* wv      = (const float*)d_in[9];
    const float* bv      = (const float*)d_in[10];
    const float* w_out   = (const float*)d_in[11];
    const float* b_out   = (const float*)d_in[12];
    float* out = (float*)d_out;

    detect_mask_kernel<<<1, 256>>>(pmask, in_sizes[2]);
    combine_weights_kernel<<<En, Cn>>>(wq, w_in, b_in, bq);

    {
        dim3 g(En / 64, (Bn * Tn) / 64);
        gemm_nt_bias<0><<<g, 256>>>(x, nullptr, nullptr, nullptr,
                                    Bn * Tn, En, Cn, SCALE_F);
    }
    {
        dim3 g(En / 64, (Bn * Sn) / 64);
        gemm_nt_bias<1><<<g, 256>>>(context, wk, bk, nullptr,
                                    Bn * Sn, En, En, 1.f);
        gemm_nt_bias<2><<<g, 256>>>(context, wv, bv, nullptr,
                                    Bn * Sn, En, En, 1.f);
    }
    {
        const int smem_bytes =
            (2 * 64 * KPITCH + 2 * 64 * VPITCH + 4 * 16 * KPITCH) * 4;  // 89088
        cudaFuncSetAttribute(attn_mma_kernel,
                             cudaFuncAttributeMaxDynamicSharedMemorySize,
                             smem_bytes);
        dim3 g(Tn / 64, Bn * Hn);
        attn_mma_kernel<<<g, 128, smem_bytes>>>(pmask);
    }
    {
        dim3 g(Cn / 64, (Bn * Tn) / 64);
        gemm_nt_bias<3><<<g, 256>>>(nullptr, w_out, b_out, out,
                                    Bn * Tn, Cn, En, 1.f);
    }
}

// round 14
// speedup vs baseline: 1.9923x; 1.1839x over previous
#include <cuda_runtime.h>

// Problem constants
#define Bn 4
#define Tn 2048
#define Sn 2048
#define Cn 256
#define En 512
#define Hn 8
#define Dn 64
#define SCALE_F 0.04419417382415922f   // 512^-0.5

#define KPITCH 68
#define VPITCH 72
#define QROWS 128      // q-rows per attention block
#define AWARPS 8       // warps per attention block

// ---------------- scratch (static device globals; no allocations) ----------
__device__ float g_Q[Bn * Tn * En];     // pre-scaled Q, then attention out
__device__ float g_K[Bn * Sn * En];     // [B*S, E]
__device__ float g_V[Bn * Sn * En];     // [B*S, E]
__device__ float g_Wc[En * Cn];         // wq @ w_in
__device__ float g_bc[En];              // bq + wq @ b_in
__device__ int   g_mask_type;           // 0=int32 words, 1=float32 words, 2=bytes

// ---------------- mask dtype detection -------------------------------------
__global__ void detect_mask_kernel(const void* __restrict__ mask, int nelem) {
    __shared__ int s_notint, s_notfloat;
    if (threadIdx.x == 0) { s_notint = 0; s_notfloat = 0; }
    __syncthreads();
    int n = nelem < 4096 ? nelem : 4096;
    const unsigned int* w = (const unsigned int*)mask;
    int ni = 0, nf = 0;
    for (int i = threadIdx.x; i < n; i += blockDim.x) {
        unsigned int v = w[i];
        if (v > 1u) ni = 1;
        if (v != 0u && v != 0x3F800000u) nf = 1;
    }
    if (ni) atomicOr(&s_notint, 1);
    if (nf) atomicOr(&s_notfloat, 1);
    __syncthreads();
    if (threadIdx.x == 0)
        g_mask_type = (s_notint == 0) ? 0 : (s_notfloat == 0 ? 1 : 2);
}

// ---------------- fold wq @ w_in -------------------------------------------
__global__ void combine_weights_kernel(const float* __restrict__ wq,
                                       const float* __restrict__ w_in,
                                       const float* __restrict__ b_in,
                                       const float* __restrict__ bq) {
    int e = blockIdx.x;
    int c = threadIdx.x;
    float acc = 0.f;
    #pragma unroll 4
    for (int j = 0; j < En; j++)
        acc = fmaf(wq[e * En + j], w_in[j * Cn + c], acc);
    g_Wc[e * Cn + c] = acc;
    if (c == 0) {
        float a = bq[e];
        for (int j = 0; j < En; j++)
            a = fmaf(wq[e * En + j], b_in[j], a);
        g_bc[e] = a;
    }
}

// ---------------- tiled NT GEMM with bias (128x128, 8x8 microtile) ----------
// C[m,n] = alpha * ( sum_k A[m,k]*B[n,k] + bias[n] )
//   MODE 0: A=param(x),       B=g_Wc,  bias=g_bc,  C=g_Q,  alpha=SCALE
//   MODE 1: A=param(context), B=param, bias=param, C=g_K
//   MODE 2: A=param(context), B=param, bias=param, C=g_V
//   MODE 3: A=g_Q (attn out), B=param, bias=param, C=param(out)
// M%128==0, N%128==0, K%16==0.
template<int MODE>
__global__ __launch_bounds__(256)
void gemm_nt_bias(const float* __restrict__ A_in, const float* __restrict__ B_in,
                  const float* __restrict__ bias_in, float* __restrict__ C_out,
                  int M, int N, int K, float alpha) {
    const float* A    = (MODE == 3) ? (const float*)g_Q : A_in;
    const float* B    = (MODE == 0) ? (const float*)g_Wc : B_in;
    const float* bias = (MODE == 0) ? (const float*)g_bc : bias_in;
    float* C;
    if      (MODE == 0) C = g_Q;
    else if (MODE == 1) C = g_K;
    else if (MODE == 2) C = g_V;
    else                C = C_out;

    const int BM = 128, BN = 128, BK = 16;
    __shared__ float As[BK][BM];
    __shared__ float Bs[BK][BN];
    int tid = threadIdx.x;
    int tx = tid & 15;          // 0..15 -> cols tx*4 and 64+tx*4
    int ty = tid >> 4;          // 0..15 -> rows ty*4 and 64+ty*4
    int bm = blockIdx.y * BM;
    int bn = blockIdx.x * BN;
    int la_row = tid >> 1;          // 0..127
    int la_col = (tid & 1) * 8;     // 0 or 8

    float acc[8][8] = {};
    const float* Ap = A + (long)(bm + la_row) * K + la_col;
    const float* Bp = B + (long)(bn + la_row) * K + la_col;

    for (int k0 = 0; k0 < K; k0 += BK) {
        float4 a0 = *(const float4*)(Ap + k0);
        float4 a1 = *(const float4*)(Ap + k0 + 4);
        float4 b0 = *(const float4*)(Bp + k0);
        float4 b1 = *(const float4*)(Bp + k0 + 4);
        As[la_col + 0][la_row] = a0.x; As[la_col + 1][la_row] = a0.y;
        As[la_col + 2][la_row] = a0.z; As[la_col + 3][la_row] = a0.w;
        As[la_col + 4][la_row] = a1.x; As[la_col + 5][la_row] = a1.y;
        As[la_col + 6][la_row] = a1.z; As[la_col + 7][la_row] = a1.w;
        Bs[la_col + 0][la_row] = b0.x; Bs[la_col + 1][la_row] = b0.y;
        Bs[la_col + 2][la_row] = b0.z; Bs[la_col + 3][la_row] = b0.w;
        Bs[la_col + 4][la_row] = b1.x; Bs[la_col + 5][la_row] = b1.y;
        Bs[la_col + 6][la_row] = b1.z; Bs[la_col + 7][la_row] = b1.w;
        __syncthreads();
        #pragma unroll
        for (int kk = 0; kk < BK; kk++) {
            float4 aA = *(const float4*)&As[kk][ty * 4];
            float4 aB = *(const float4*)&As[kk][64 + ty * 4];
            float4 bA = *(const float4*)&Bs[kk][tx * 4];
            float4 bB = *(const float4*)&Bs[kk][64 + tx * 4];
            float a[8] = {aA.x, aA.y, aA.z, aA.w, aB.x, aB.y, aB.z, aB.w};
            float b[8] = {bA.x, bA.y, bA.z, bA.w, bB.x, bB.y, bB.z, bB.w};
            #pragma unroll
            for (int i = 0; i < 8; i++)
                #pragma unroll
                for (int j = 0; j < 8; j++)
                    acc[i][j] = fmaf(a[i], b[j], acc[i][j]);
        }
        __syncthreads();
    }
    float bb[8];
    #pragma unroll
    for (int j = 0; j < 4; j++) bb[j] = bias[bn + tx * 4 + j];
    #pragma unroll
    for (int j = 0; j < 4; j++) bb[4 + j] = bias[bn + 64 + tx * 4 + j];
    #pragma unroll
    for (int i = 0; i < 8; i++) {
        int row = bm + ((i < 4) ? (ty * 4 + i) : (64 + ty * 4 + i - 4));
        float4 r0, r1;
        r0.x = alpha * (acc[i][0] + bb[0]);
        r0.y = alpha * (acc[i][1] + bb[1]);
        r0.z = alpha * (acc[i][2] + bb[2]);
        r0.w = alpha * (acc[i][3] + bb[3]);
        r1.x = alpha * (acc[i][4] + bb[4]);
        r1.y = alpha * (acc[i][5] + bb[5]);
        r1.z = alpha * (acc[i][6] + bb[6]);
        r1.w = alpha * (acc[i][7] + bb[7]);
        *(float4*)&C[(long)row * N + bn + tx * 4] = r0;
        *(float4*)&C[(long)row * N + bn + 64 + tx * 4] = r1;
    }
}

// ---------------- tf32 warp-MMA helper --------------------------------------
__device__ __forceinline__ void mma_tf32(float& d0, float& d1, float& d2, float& d3,
                                         float a0, float a1, float a2, float a3,
                                         float b0, float b1) {
    unsigned ua0 = __float_as_uint(a0), ua1 = __float_as_uint(a1);
    unsigned ua2 = __float_as_uint(a2), ua3 = __float_as_uint(a3);
    unsigned ub0 = __float_as_uint(b0), ub1 = __float_as_uint(b1);
    asm volatile(
        "mma.sync.aligned.m16n8k8.row.col.f32.tf32.tf32.f32 "
        "{%0,%1,%2,%3}, {%4,%5,%6,%7}, {%8,%9}, {%0,%1,%2,%3};"
        : "+f"(d0), "+f"(d1), "+f"(d2), "+f"(d3)
        : "r"(ua0), "r"(ua1), "r"(ua2), "r"(ua3), "r"(ub0), "r"(ub1));
}

__device__ __forceinline__ void cpasync16(unsigned smem_addr, const void* gptr) {
    asm volatile("cp.async.cg.shared.global [%0], [%1], 16;"
                 :: "r"(smem_addr), "l"(gptr));
}
__device__ __forceinline__ void cpasync_commit() {
    asm volatile("cp.async.commit_group;");
}
__device__ __forceinline__ void cpasync_wait0() {
    asm volatile("cp.async.wait_group 0;" ::: "memory");
}

// ---------------- flash attention via tensor-core MMA + cp.async ------------
// grid: (T/128, B*H), block: 256 threads (8 warps). Warp w owns q-rows
// [16w,16w+16) of a 128-row q-tile; all 8 warps share each K/V tile ->
// 16 warps/SM (4/SMSP) for latency hiding, and K/V smem-fill per q-row halves.
__global__ __launch_bounds__(256)
void attn_mma_kernel(const void* __restrict__ mask) {
    extern __shared__ float smem[];
    // layout: Ks[2][64][KPITCH] | Vs[2][64][VPITCH] | Pw[AWARPS][16][KPITCH]
    float (*Ks)[64][KPITCH] = (float(*)[64][KPITCH])smem;
    float (*Vs)[64][VPITCH] = (float(*)[64][VPITCH])(smem + 2 * 64 * KPITCH);
    float (*Pw)[KPITCH] = (float(*)[KPITCH])
        (smem + 2 * 64 * KPITCH + 2 * 64 * VPITCH + (threadIdx.x >> 5) * 16 * KPITCH);

    const int bh = blockIdx.y;
    const int b = bh / Hn, h = bh % Hn;
    const int qbase = blockIdx.x * QROWS;
    const int tid = threadIdx.x;
    const int warp = tid >> 5;
    const int lane = tid & 31;
    const int grp = lane >> 2;
    const int t4 = lane & 3;
    const int mtype = g_mask_type;

    unsigned sb;
    asm("{ .reg .u64 t; cvta.to.shared.u64 t, %1; cvt.u32.u64 %0, t; }"
        : "=r"(sb) : "l"(smem));
    const unsigned ks_u32 = sb;
    const unsigned vs_u32 = sb + 2 * 64 * KPITCH * 4;

    // Q A-fragments for this warp's 16 rows (pre-scaled by SCALE)
    const float* Qp = g_Q + (long)(b * Tn + qbase + warp * 16) * En + h * Dn;
    float qf[8][4];
    #pragma unroll
    for (int ks = 0; ks < 8; ks++) {
        qf[ks][0] = Qp[(long)grp * En + 8 * ks + t4];
        qf[ks][1] = Qp[(long)(grp + 8) * En + 8 * ks + t4];
        qf[ks][2] = Qp[(long)grp * En + 8 * ks + t4 + 4];
        qf[ks][3] = Qp[(long)(grp + 8) * En + 8 * ks + t4 + 4];
    }

    // copy geometry: 256 threads cover 64 rows x 64 cols: row = tid/4,
    // 16-col quarter = (tid&3)*16, 4 x 16B chunks each for K and V.
    const int crow = tid >> 2;
    const int ccol = (tid & 3) * 16;
    const float* Kg = g_K + (long)(b * Sn + crow) * En + h * Dn + ccol;
    const float* Vg = g_V + (long)(b * Sn + crow) * En + h * Dn + ccol;
    const unsigned kdst = ks_u32 + (crow * KPITCH + ccol) * 4;
    const unsigned vdst = vs_u32 + (crow * VPITCH + ccol) * 4;
    const unsigned kbufstride = 64 * KPITCH * 4;
    const unsigned vbufstride = 64 * VPITCH * 4;

    auto prefetch = [&](int buf, int s0) {
        const float* kg = Kg + (long)s0 * En;
        const float* vg = Vg + (long)s0 * En;
        unsigned kd = kdst + buf * kbufstride;
        unsigned vd = vdst + buf * vbufstride;
        #pragma unroll
        for (int i = 0; i < 4; i++) {
            cpasync16(kd + 16 * i, kg + 4 * i);
            cpasync16(vd + 16 * i, vg + 4 * i);
        }
        cpasync_commit();
    };

    float o[8][4];
    #pragma unroll
    for (int nt = 0; nt < 8; nt++)
        o[nt][0] = o[nt][1] = o[nt][2] = o[nt][3] = 0.f;
    float m0 = -1e30f, m1 = -1e30f, l0 = 0.f, l1 = 0.f;

    int cur = 0;
    prefetch(0, 0);

    #pragma unroll 1
    for (int it = 0; it < Sn / 64; ++it) {
        const int s0 = it * 64;
        cpasync_wait0();
        __syncthreads();
        if (it + 1 < Sn / 64) prefetch(cur ^ 1, s0 + 64);

        // ---- mask pack in registers: lane l<16 packs row qbase+16*warp+l ----
        unsigned long long mypack = 0ull;
        if (lane < 16) {
            long mbase = (long)b * Tn * Sn + (long)(qbase + 16 * warp + lane) * Sn + s0;
            if (mtype == 2) {
                const unsigned long long* mp =
                    (const unsigned long long*)((const unsigned char*)mask + mbase);
                #pragma unroll
                for (int w = 0; w < 8; w++) {
                    unsigned long long v = mp[w];
                    #pragma unroll
                    for (int k = 0; k < 8; k++)
                        if ((v >> (8 * k)) & 0xffull) mypack |= 1ull << (w * 8 + k);
                }
            } else {
                const int4* mp = (const int4*)((const int*)mask + mbase);
                #pragma unroll
                for (int w = 0; w < 16; w++) {
                    int4 v = mp[w];
                    if (v.x) mypack |= 1ull << (w * 4 + 0);
                    if (v.y) mypack |= 1ull << (w * 4 + 1);
                    if (v.z) mypack |= 1ull << (w * 4 + 2);
                    if (v.w) mypack |= 1ull << (w * 4 + 3);
                }
            }
        }
        unsigned long long mr0 = __shfl_sync(0xffffffffu, mypack, grp);
        unsigned long long mr1 = __shfl_sync(0xffffffffu, mypack, grp + 8);

        // ---- S = Q K^T ----
        float sv[8][4];
        #pragma unroll
        for (int nt = 0; nt < 8; nt++) {
            float c0r = 0.f, c1r = 0.f, c2r = 0.f, c3r = 0.f;
            #pragma unroll
            for (int ks = 0; ks < 8; ks++) {
                float b0 = Ks[cur][8 * nt + grp][8 * ks + t4];
                float b1 = Ks[cur][8 * nt + grp][8 * ks + t4 + 4];
                mma_tf32(c0r, c1r, c2r, c3r,
                         qf[ks][0], qf[ks][1], qf[ks][2], qf[ks][3], b0, b1);
            }
            sv[nt][0] = c0r; sv[nt][1] = c1r; sv[nt][2] = c2r; sv[nt][3] = c3r;
        }

        // ---- mask ----
        #pragma unroll
        for (int nt = 0; nt < 8; nt++) {
            int col = 8 * nt + 2 * t4;
            if ((mr0 >> col) & 1ull)       sv[nt][0] = -1e9f;
            if ((mr0 >> (col + 1)) & 1ull) sv[nt][1] = -1e9f;
            if ((mr1 >> col) & 1ull)       sv[nt][2] = -1e9f;
            if ((mr1 >> (col + 1)) & 1ull) sv[nt][3] = -1e9f;
        }

        // ---- online softmax ----
        float tmax0 = -1e30f, tmax1 = -1e30f;
        #pragma unroll
        for (int nt = 0; nt < 8; nt++) {
            tmax0 = fmaxf(tmax0, fmaxf(sv[nt][0], sv[nt][1]));
            tmax1 = fmaxf(tmax1, fmaxf(sv[nt][2], sv[nt][3]));
        }
        tmax0 = fmaxf(tmax0, __shfl_xor_sync(0xffffffffu, tmax0, 1));
        tmax0 = fmaxf(tmax0, __shfl_xor_sync(0xffffffffu, tmax0, 2));
        tmax1 = fmaxf(tmax1, __shfl_xor_sync(0xffffffffu, tmax1, 1));
        tmax1 = fmaxf(tmax1, __shfl_xor_sync(0xffffffffu, tmax1, 2));

        float m0n = fmaxf(m0, tmax0);
        float m1n = fmaxf(m1, tmax1);
        float corr0 = __expf(m0 - m0n);
        float corr1 = __expf(m1 - m1n);
        m0 = m0n; m1 = m1n;

        float lp0 = 0.f, lp1 = 0.f;
        #pragma unroll
        for (int nt = 0; nt < 8; nt++) {
            float p0 = __expf(sv[nt][0] - m0);
            float p1 = __expf(sv[nt][1] - m0);
            float p2 = __expf(sv[nt][2] - m1);
            float p3 = __expf(sv[nt][3] - m1);
            lp0 += p0 + p1; lp1 += p2 + p3;
            sv[nt][0] = p0; sv[nt][1] = p1; sv[nt][2] = p2; sv[nt][3] = p3;
        }
        l0 = l0 * corr0 + lp0;
        l1 = l1 * corr1 + lp1;
        #pragma unroll
        for (int nt = 0; nt < 8; nt++) {
            o[nt][0] *= corr0; o[nt][1] *= corr0;
            o[nt][2] *= corr1; o[nt][3] *= corr1;
        }

        // ---- stage P (C-layout -> per-warp smem) ----
        #pragma unroll
        for (int nt = 0; nt < 8; nt++) {
            int col = 8 * nt + 2 * t4;
            *(float2*)&Pw[grp][col]     = make_float2(sv[nt][0], sv[nt][1]);
            *(float2*)&Pw[grp + 8][col] = make_float2(sv[nt][2], sv[nt][3]);
        }
        __syncwarp();

        // ---- O += P V ----
        #pragma unroll
        for (int ks = 0; ks < 8; ks++) {
            float a0 = Pw[grp][8 * ks + t4];
            float a1 = Pw[grp + 8][8 * ks + t4];
            float a2 = Pw[grp][8 * ks + t4 + 4];
            float a3 = Pw[grp + 8][8 * ks + t4 + 4];
            #pragma unroll
            for (int nt = 0; nt < 8; nt++) {
                float b0 = Vs[cur][8 * ks + t4][8 * nt + grp];
                float b1 = Vs[cur][8 * ks + t4 + 4][8 * nt + grp];
                mma_tf32(o[nt][0], o[nt][1], o[nt][2], o[nt][3],
                         a0, a1, a2, a3, b0, b1);
            }
        }
        __syncwarp();
        cur ^= 1;
    }

    // final normalize + in-place write over g_Q
    l0 += __shfl_xor_sync(0xffffffffu, l0, 1);
    l0 += __shfl_xor_sync(0xffffffffu, l0, 2);
    l1 += __shfl_xor_sync(0xffffffffu, l1, 1);
    l1 += __shfl_xor_sync(0xffffffffu, l1, 2);
    float inv0 = 1.f / l0;
    float inv1 = 1.f / l1;

    float* Op = g_Q + (long)(b * Tn + qbase + warp * 16) * En + h * Dn;
    #pragma unroll
    for (int nt = 0; nt < 8; nt++) {
        int col = 8 * nt + 2 * t4;
        *(float2*)&Op[(long)grp * En + col] =
            make_float2(o[nt][0] * inv0, o[nt][1] * inv0);
        *(float2*)&Op[(long)(grp + 8) * En + col] =
            make_float2(o[nt][2] * inv1, o[nt][3] * inv1);
    }
}

// ---------------- launch -----------------------------------------------------
extern "C" void kernel_launch(void* const* d_in, const int* in_sizes, int n_in,
                              void* d_out, int out_size) {
    const float* x       = (const float*)d_in[0];
    const float* context = (const float*)d_in[1];
    const void*  pmask   = d_in[2];
    const float* w_in    = (const float*)d_in[3];
    const float* b_in    = (const float*)d_in[4];
    const float* wq      = (const float*)d_in[5];
    const float* bq      = (const float*)d_in[6];
    const float* wk      = (const float*)d_in[7];
    const float* bk      = (const float*)d_in[8];
    const float* wv      = (const float*)d_in[9];
    const float* bv      = (const float*)d_in[10];
    const float* w_out   = (const float*)d_in[11];
    const float* b_out   = (const float*)d_in[12];
    float* out = (float*)d_out;

    detect_mask_kernel<<<1, 256>>>(pmask, in_sizes[2]);
    combine_weights_kernel<<<En, Cn>>>(wq, w_in, b_in, bq);

    // Q = SCALE * (x @ Wc^T + bc) -> g_Q   [8192,512], K=256
    {
        dim3 g(En / 128, (Bn * Tn) / 128);
        gemm_nt_bias<0><<<g, 256>>>(x, nullptr, nullptr, nullptr,
                                    Bn * Tn, En, Cn, SCALE_F);
    }
    // K/V = context @ w^T + b -> g_K / g_V   [8192,512], K=512
    {
        dim3 g(En / 128, (Bn * Sn) / 128);
        gemm_nt_bias<1><<<g, 256>>>(context, wk, bk, nullptr,
                                    Bn * Sn, En, En, 1.f);
        gemm_nt_bias<2><<<g, 256>>>(context, wv, bv, nullptr,
                                    Bn * Sn, En, En, 1.f);
    }
    // attention (tensor-core MMA, 128 q-rows/block, in place over g_Q)
    {
        const int smem_bytes =
            (2 * 64 * KPITCH + 2 * 64 * VPITCH + AWARPS * 16 * KPITCH) * 4;  // 106496
        cudaFuncSetAttribute(attn_mma_kernel,
                             cudaFuncAttributeMaxDynamicSharedMemorySize,
                             smem_bytes);
        dim3 g(Tn / QROWS, Bn * Hn);
        attn_mma_kernel<<<g, 32 * AWARPS, smem_bytes>>>(pmask);
    }
    // out = O @ w_out^T + b_out   [8192,256], K=512
    {
        dim3 g(Cn / 128, (Bn * Tn) / 128);
        gemm_nt_bias<3><<<g, 256>>>(nullptr, w_out, b_out, out,
                                    Bn * Tn, Cn, En, 1.f);
    }
}

// round 16
// speedup vs baseline: 2.0795x; 1.0438x over previous
#include <cuda_runtime.h>

// Problem constants
#define Bn 4
#define Tn 2048
#define Sn 2048
#define Cn 256
#define En 512
#define Hn 8
#define Dn 64
#define SCALE_F 0.04419417382415922f   // 512^-0.5

#define KPITCH 68
#define VPITCH 72
#define QROWS 128      // q-rows per attention block
#define AWARPS 8       // warps per attention block

typedef unsigned long long u64t;

// ---------------- packed f32x2 helpers --------------------------------------
__device__ __forceinline__ u64t fma2(u64t a, u64t b, u64t c) {
    u64t d; asm("fma.rn.f32x2 %0, %1, %2, %3;" : "=l"(d) : "l"(a), "l"(b), "l"(c));
    return d;
}
__device__ __forceinline__ u64t pack2dup(float a) {
    u64t d; asm("mov.b64 %0, {%1, %1};" : "=l"(d) : "f"(a));
    return d;
}
__device__ __forceinline__ float2 unpack2(u64t v) {
    float lo, hi; asm("mov.b64 {%0, %1}, %2;" : "=f"(lo), "=f"(hi) : "l"(v));
    return make_float2(lo, hi);
}

// ---------------- scratch (static device globals; no allocations) ----------
__device__ float g_Q[Bn * Tn * En];     // pre-scaled Q, then attention out
__device__ float g_K[Bn * Sn * En];     // [B*S, E]
__device__ float g_V[Bn * Sn * En];     // [B*S, E]
__device__ float g_Wc[En * Cn];         // wq @ w_in
__device__ float g_bc[En];              // bq + wq @ b_in
__device__ int   g_mask_type;           // 0=int32 words, 1=float32 words, 2=bytes

// ---------------- mask dtype detection -------------------------------------
__global__ void detect_mask_kernel(const void* __restrict__ mask, int nelem) {
    __shared__ int s_notint, s_notfloat;
    if (threadIdx.x == 0) { s_notint = 0; s_notfloat = 0; }
    __syncthreads();
    int n = nelem < 4096 ? nelem : 4096;
    const unsigned int* w = (const unsigned int*)mask;
    int ni = 0, nf = 0;
    for (int i = threadIdx.x; i < n; i += blockDim.x) {
        unsigned int v = w[i];
        if (v > 1u) ni = 1;
        if (v != 0u && v != 0x3F800000u) nf = 1;
    }
    if (ni) atomicOr(&s_notint, 1);
    if (nf) atomicOr(&s_notfloat, 1);
    __syncthreads();
    if (threadIdx.x == 0)
        g_mask_type = (s_notint == 0) ? 0 : (s_notfloat == 0 ? 1 : 2);
}

// ---------------- fold wq @ w_in -------------------------------------------
__global__ void combine_weights_kernel(const float* __restrict__ wq,
                                       const float* __restrict__ w_in,
                                       const float* __restrict__ b_in,
                                       const float* __restrict__ bq) {
    int e = blockIdx.x;
    int c = threadIdx.x;
    float acc = 0.f;
    #pragma unroll 4
    for (int j = 0; j < En; j++)
        acc = fmaf(wq[e * En + j], w_in[j * Cn + c], acc);
    g_Wc[e * Cn + c] = acc;
    if (c == 0) {
        float a = bq[e];
        for (int j = 0; j < En; j++)
            a = fmaf(wq[e * En + j], b_in[j], a);
        g_bc[e] = a;
    }
}

// ---------------- tiled NT GEMM (128x128, 8x8, f32x2, reg double-buffer) ----
// C[m,n] = alpha * ( sum_k A[m,k]*B[n,k] + bias[n] )
//   MODE 0: A=param(x),       B=g_Wc,  bias=g_bc,  C=g_Q,  alpha=SCALE
//   MODE 1: A=param(context), B=param, bias=param, C=g_K
//   MODE 2: A=param(context), B=param, bias=param, C=g_V
//   MODE 3: A=g_Q (attn out), B=param, bias=param, C=param(out)
// Per-output-element fp32 accumulation order identical to scalar version
// (f32x2 is lane-wise IEEE fmaf).
template<int MODE>
__global__ __launch_bounds__(256)
void gemm_nt_bias(const float* __restrict__ A_in, const float* __restrict__ B_in,
                  const float* __restrict__ bias_in, float* __restrict__ C_out,
                  int M, int N, int K, float alpha) {
    const float* A    = (MODE == 3) ? (const float*)g_Q : A_in;
    const float* B    = (MODE == 0) ? (const float*)g_Wc : B_in;
    const float* bias = (MODE == 0) ? (const float*)g_bc : bias_in;
    float* C;
    if      (MODE == 0) C = g_Q;
    else if (MODE == 1) C = g_K;
    else if (MODE == 2) C = g_V;
    else                C = C_out;

    const int BM = 128, BN = 128, BK = 16;
    __shared__ float As[BK][BM];
    __shared__ float Bs[BK][BN];
    int tid = threadIdx.x;
    int tx = tid & 15;          // cols tx*4 and 64+tx*4
    int ty = tid >> 4;          // rows ty*4 and 64+ty*4
    int bm = blockIdx.y * BM;
    int bn = blockIdx.x * BN;
    int la_row = tid >> 1;          // 0..127
    int la_col = (tid & 1) * 8;     // 0 or 8

    u64t accp[8][4];
    #pragma unroll
    for (int i = 0; i < 8; i++)
        #pragma unroll
        for (int j = 0; j < 4; j++) accp[i][j] = 0ull;

    const float* Ap = A + (long)(bm + la_row) * K + la_col;
    const float* Bp = B + (long)(bn + la_row) * K + la_col;

    // prologue: first tile into registers
    float4 ra0 = *(const float4*)(Ap);
    float4 ra1 = *(const float4*)(Ap + 4);
    float4 rb0 = *(const float4*)(Bp);
    float4 rb1 = *(const float4*)(Bp + 4);

    for (int k0 = 0; k0 < K; k0 += BK) {
        As[la_col + 0][la_row] = ra0.x; As[la_col + 1][la_row] = ra0.y;
        As[la_col + 2][la_row] = ra0.z; As[la_col + 3][la_row] = ra0.w;
        As[la_col + 4][la_row] = ra1.x; As[la_col + 5][la_row] = ra1.y;
        As[la_col + 6][la_row] = ra1.z; As[la_col + 7][la_row] = ra1.w;
        Bs[la_col + 0][la_row] = rb0.x; Bs[la_col + 1][la_row] = rb0.y;
        Bs[la_col + 2][la_row] = rb0.z; Bs[la_col + 3][la_row] = rb0.w;
        Bs[la_col + 4][la_row] = rb1.x; Bs[la_col + 5][la_row] = rb1.y;
        Bs[la_col + 6][la_row] = rb1.z; Bs[la_col + 7][la_row] = rb1.w;
        __syncthreads();

        // prefetch next tile while computing this one
        if (k0 + BK < K) {
            ra0 = *(const float4*)(Ap + k0 + BK);
            ra1 = *(const float4*)(Ap + k0 + BK + 4);
            rb0 = *(const float4*)(Bp + k0 + BK);
            rb1 = *(const float4*)(Bp + k0 + BK + 4);
        }

        #pragma unroll
        for (int kk = 0; kk < BK; kk++) {
            float4 aA = *(const float4*)&As[kk][ty * 4];
            float4 aB = *(const float4*)&As[kk][64 + ty * 4];
            ulonglong2 bA = *(const ulonglong2*)&Bs[kk][tx * 4];
            ulonglong2 bB = *(const ulonglong2*)&Bs[kk][64 + tx * 4];
            u64t bp0 = bA.x, bp1 = bA.y, bp2 = bB.x, bp3 = bB.y;
            float a[8] = {aA.x, aA.y, aA.z, aA.w, aB.x, aB.y, aB.z, aB.w};
            #pragma unroll
            for (int i = 0; i < 8; i++) {
                u64t ap = pack2dup(a[i]);
                accp[i][0] = fma2(ap, bp0, accp[i][0]);
                accp[i][1] = fma2(ap, bp1, accp[i][1]);
                accp[i][2] = fma2(ap, bp2, accp[i][2]);
                accp[i][3] = fma2(ap, bp3, accp[i][3]);
            }
        }
        __syncthreads();
    }

    float bb[8];
    #pragma unroll
    for (int j = 0; j < 4; j++) bb[j] = bias[bn + tx * 4 + j];
    #pragma unroll
    for (int j = 0; j < 4; j++) bb[4 + j] = bias[bn + 64 + tx * 4 + j];
    #pragma unroll
    for (int i = 0; i < 8; i++) {
        int row = bm + ((i < 4) ? (ty * 4 + i) : (64 + ty * 4 + i - 4));
        float2 p0 = unpack2(accp[i][0]);
        float2 p1 = unpack2(accp[i][1]);
        float2 p2 = unpack2(accp[i][2]);
        float2 p3 = unpack2(accp[i][3]);
        float4 r0, r1;
        r0.x = alpha * (p0.x + bb[0]);
        r0.y = alpha * (p0.y + bb[1]);
        r0.z = alpha * (p1.x + bb[2]);
        r0.w = alpha * (p1.y + bb[3]);
        r1.x = alpha * (p2.x + bb[4]);
        r1.y = alpha * (p2.y + bb[5]);
        r1.z = alpha * (p3.x + bb[6]);
        r1.w = alpha * (p3.y + bb[7]);
        *(float4*)&C[(long)row * N + bn + tx * 4] = r0;
        *(float4*)&C[(long)row * N + bn + 64 + tx * 4] = r1;
    }
}

// ---------------- tf32 warp-MMA helper --------------------------------------
__device__ __forceinline__ void mma_tf32(float& d0, float& d1, float& d2, float& d3,
                                         float a0, float a1, float a2, float a3,
                                         float b0, float b1) {
    unsigned ua0 = __float_as_uint(a0), ua1 = __float_as_uint(a1);
    unsigned ua2 = __float_as_uint(a2), ua3 = __float_as_uint(a3);
    unsigned ub0 = __float_as_uint(b0), ub1 = __float_as_uint(b1);
    asm volatile(
        "mma.sync.aligned.m16n8k8.row.col.f32.tf32.tf32.f32 "
        "{%0,%1,%2,%3}, {%4,%5,%6,%7}, {%8,%9}, {%0,%1,%2,%3};"
        : "+f"(d0), "+f"(d1), "+f"(d2), "+f"(d3)
        : "r"(ua0), "r"(ua1), "r"(ua2), "r"(ua3), "r"(ub0), "r"(ub1));
}

__device__ __forceinline__ void cpasync16(unsigned smem_addr, const void* gptr) {
    asm volatile("cp.async.cg.shared.global [%0], [%1], 16;"
                 :: "r"(smem_addr), "l"(gptr));
}
__device__ __forceinline__ void cpasync_commit() {
    asm volatile("cp.async.commit_group;");
}
__device__ __forceinline__ void cpasync_wait0() {
    asm volatile("cp.async.wait_group 0;" ::: "memory");
}

// ---------------- flash attention via tensor-core MMA + cp.async ------------
// (unchanged from R14)
__global__ __launch_bounds__(256)
void attn_mma_kernel(const void* __restrict__ mask) {
    extern __shared__ float smem[];
    float (*Ks)[64][KPITCH] = (float(*)[64][KPITCH])smem;
    float (*Vs)[64][VPITCH] = (float(*)[64][VPITCH])(smem + 2 * 64 * KPITCH);
    float (*Pw)[KPITCH] = (float(*)[KPITCH])
        (smem + 2 * 64 * KPITCH + 2 * 64 * VPITCH + (threadIdx.x >> 5) * 16 * KPITCH);

    const int bh = blockIdx.y;
    const int b = bh / Hn, h = bh % Hn;
    const int qbase = blockIdx.x * QROWS;
    const int tid = threadIdx.x;
    const int warp = tid >> 5;
    const int lane = tid & 31;
    const int grp = lane >> 2;
    const int t4 = lane & 3;
    const int mtype = g_mask_type;

    unsigned sb;
    asm("{ .reg .u64 t; cvta.to.shared.u64 t, %1; cvt.u32.u64 %0, t; }"
        : "=r"(sb) : "l"(smem));
    const unsigned ks_u32 = sb;
    const unsigned vs_u32 = sb + 2 * 64 * KPITCH * 4;

    const float* Qp = g_Q + (long)(b * Tn + qbase + warp * 16) * En + h * Dn;
    float qf[8][4];
    #pragma unroll
    for (int ks = 0; ks < 8; ks++) {
        qf[ks][0] = Qp[(long)grp * En + 8 * ks + t4];
        qf[ks][1] = Qp[(long)(grp + 8) * En + 8 * ks + t4];
        qf[ks][2] = Qp[(long)grp * En + 8 * ks + t4 + 4];
        qf[ks][3] = Qp[(long)(grp + 8) * En + 8 * ks + t4 + 4];
    }

    const int crow = tid >> 2;
    const int ccol = (tid & 3) * 16;
    const float* Kg = g_K + (long)(b * Sn + crow) * En + h * Dn + ccol;
    const float* Vg = g_V + (long)(b * Sn + crow) * En + h * Dn + ccol;
    const unsigned kdst = ks_u32 + (crow * KPITCH + ccol) * 4;
    const unsigned vdst = vs_u32 + (crow * VPITCH + ccol) * 4;
    const unsigned kbufstride = 64 * KPITCH * 4;
    const unsigned vbufstride = 64 * VPITCH * 4;

    auto prefetch = [&](int buf, int s0) {
        const float* kg = Kg + (long)s0 * En;
        const float* vg = Vg + (long)s0 * En;
        unsigned kd = kdst + buf * kbufstride;
        unsigned vd = vdst + buf * vbufstride;
        #pragma unroll
        for (int i = 0; i < 4; i++) {
            cpasync16(kd + 16 * i, kg + 4 * i);
            cpasync16(vd + 16 * i, vg + 4 * i);
        }
        cpasync_commit();
    };

    float o[8][4];
    #pragma unroll
    for (int nt = 0; nt < 8; nt++)
        o[nt][0] = o[nt][1] = o[nt][2] = o[nt][3] = 0.f;
    float m0 = -1e30f, m1 = -1e30f, l0 = 0.f, l1 = 0.f;

    int cur = 0;
    prefetch(0, 0);

    #pragma unroll 1
    for (int it = 0; it < Sn / 64; ++it) {
        const int s0 = it * 64;
        cpasync_wait0();
        __syncthreads();
        if (it + 1 < Sn / 64) prefetch(cur ^ 1, s0 + 64);

        unsigned long long mypack = 0ull;
        if (lane < 16) {
            long mbase = (long)b * Tn * Sn + (long)(qbase + 16 * warp + lane) * Sn + s0;
            if (mtype == 2) {
                const unsigned long long* mp =
                    (const unsigned long long*)((const unsigned char*)mask + mbase);
                #pragma unroll
                for (int w = 0; w < 8; w++) {
                    unsigned long long v = mp[w];
                    #pragma unroll
                    for (int k = 0; k < 8; k++)
                        if ((v >> (8 * k)) & 0xffull) mypack |= 1ull << (w * 8 + k);
                }
            } else {
                const int4* mp = (const int4*)((const int*)mask + mbase);
                #pragma unroll
                for (int w = 0; w < 16; w++) {
                    int4 v = mp[w];
                    if (v.x) mypack |= 1ull << (w * 4 + 0);
                    if (v.y) mypack |= 1ull << (w * 4 + 1);
                    if (v.z) mypack |= 1ull << (w * 4 + 2);
                    if (v.w) mypack |= 1ull << (w * 4 + 3);
                }
            }
        }
        unsigned long long mr0 = __shfl_sync(0xffffffffu, mypack, grp);
        unsigned long long mr1 = __shfl_sync(0xffffffffu, mypack, grp + 8);

        float sv[8][4];
        #pragma unroll
        for (int nt = 0; nt < 8; nt++) {
            float c0r = 0.f, c1r = 0.f, c2r = 0.f, c3r = 0.f;
            #pragma unroll
            for (int ks = 0; ks < 8; ks++) {
                float b0 = Ks[cur][8 * nt + grp][8 * ks + t4];
                float b1 = Ks[cur][8 * nt + grp][8 * ks + t4 + 4];
                mma_tf32(c0r, c1r, c2r, c3r,
                         qf[ks][0], qf[ks][1], qf[ks][2], qf[ks][3], b0, b1);
            }
            sv[nt][0] = c0r; sv[nt][1] = c1r; sv[nt][2] = c2r; sv[nt][3] = c3r;
        }

        #pragma unroll
        for (int nt = 0; nt < 8; nt++) {
            int col = 8 * nt + 2 * t4;
            if ((mr0 >> col) & 1ull)       sv[nt][0] = -1e9f;
            if ((mr0 >> (col + 1)) & 1ull) sv[nt][1] = -1e9f;
            if ((mr1 >> col) & 1ull)       sv[nt][2] = -1e9f;
            if ((mr1 >> (col + 1)) & 1ull) sv[nt][3] = -1e9f;
        }

        float tmax0 = -1e30f, tmax1 = -1e30f;
        #pragma unroll
        for (int nt = 0; nt < 8; nt++) {
            tmax0 = fmaxf(tmax0, fmaxf(sv[nt][0], sv[nt][1]));
            tmax1 = fmaxf(tmax1, fmaxf(sv[nt][2], sv[nt][3]));
        }
        tmax0 = fmaxf(tmax0, __shfl_xor_sync(0xffffffffu, tmax0, 1));
        tmax0 = fmaxf(tmax0, __shfl_xor_sync(0xffffffffu, tmax0, 2));
        tmax1 = fmaxf(tmax1, __shfl_xor_sync(0xffffffffu, tmax1, 1));
        tmax1 = fmaxf(tmax1, __shfl_xor_sync(0xffffffffu, tmax1, 2));

        float m0n = fmaxf(m0, tmax0);
        float m1n = fmaxf(m1, tmax1);
        float corr0 = __expf(m0 - m0n);
        float corr1 = __expf(m1 - m1n);
        m0 = m0n; m1 = m1n;

        float lp0 = 0.f, lp1 = 0.f;
        #pragma unroll
        for (int nt = 0; nt < 8; nt++) {
            float p0 = __expf(sv[nt][0] - m0);
            float p1 = __expf(sv[nt][1] - m0);
            float p2 = __expf(sv[nt][2] - m1);
            float p3 = __expf(sv[nt][3] - m1);
            lp0 += p0 + p1; lp1 += p2 + p3;
            sv[nt][0] = p0; sv[nt][1] = p1; sv[nt][2] = p2; sv[nt][3] = p3;
        }
        l0 = l0 * corr0 + lp0;
        l1 = l1 * corr1 + lp1;
        #pragma unroll
        for (int nt = 0; nt < 8; nt++) {
            o[nt][0] *= corr0; o[nt][1] *= corr0;
            o[nt][2] *= corr1; o[nt][3] *= corr1;
        }

        #pragma unroll
        for (int nt = 0; nt < 8; nt++) {
            int col = 8 * nt + 2 * t4;
            *(float2*)&Pw[grp][col]     = make_float2(sv[nt][0], sv[nt][1]);
            *(float2*)&Pw[grp + 8][col] = make_float2(sv[nt][2], sv[nt][3]);
        }
        __syncwarp();

        #pragma unroll
        for (int ks = 0; ks < 8; ks++) {
            float a0 = Pw[grp][8 * ks + t4];
            float a1 = Pw[grp + 8][8 * ks + t4];
            float a2 = Pw[grp][8 * ks + t4 + 4];
            float a3 = Pw[grp + 8][8 * ks + t4 + 4];
            #pragma unroll
            for (int nt = 0; nt < 8; nt++) {
                float b0 = Vs[cur][8 * ks + t4][8 * nt + grp];
                float b1 = Vs[cur][8 * ks + t4 + 4][8 * nt + grp];
                mma_tf32(o[nt][0], o[nt][1], o[nt][2], o[nt][3],
                         a0, a1, a2, a3, b0, b1);
            }
        }
        __syncwarp();
        cur ^= 1;
    }

    l0 += __shfl_xor_sync(0xffffffffu, l0, 1);
    l0 += __shfl_xor_sync(0xffffffffu, l0, 2);
    l1 += __shfl_xor_sync(0xffffffffu, l1, 1);
    l1 += __shfl_xor_sync(0xffffffffu, l1, 2);
    float inv0 = 1.f / l0;
    float inv1 = 1.f / l1;

    float* Op = g_Q + (long)(b * Tn + qbase + warp * 16) * En + h * Dn;
    #pragma unroll
    for (int nt = 0; nt < 8; nt++) {
        int col = 8 * nt + 2 * t4;
        *(float2*)&Op[(long)grp * En + col] =
            make_float2(o[nt][0] * inv0, o[nt][1] * inv0);
        *(float2*)&Op[(long)(grp + 8) * En + col] =
            make_float2(o[nt][2] * inv1, o[nt][3] * inv1);
    }
}

// ---------------- launch -----------------------------------------------------
extern "C" void kernel_launch(void* const* d_in, const int* in_sizes, int n_in,
                              void* d_out, int out_size) {
    const float* x       = (const float*)d_in[0];
    const float* context = (const float*)d_in[1];
    const void*  pmask   = d_in[2];
    const float* w_in    = (const float*)d_in[3];
    const float* b_in    = (const float*)d_in[4];
    const float* wq      = (const float*)d_in[5];
    const float* bq      = (const float*)d_in[6];
    const float* wk      = (const float*)d_in[7];
    const float* bk      = (const float*)d_in[8];
    const float* wv      = (const float*)d_in[9];
    const float* bv      = (const float*)d_in[10];
    const float* w_out   = (const float*)d_in[11];
    const float* b_out   = (const float*)d_in[12];
    float* out = (float*)d_out;

    detect_mask_kernel<<<1, 256>>>(pmask, in_sizes[2]);
    combine_weights_kernel<<<En, Cn>>>(wq, w_in, b_in, bq);

    // Q = SCALE * (x @ Wc^T + bc) -> g_Q   [8192,512], K=256
    {
        dim3 g(En / 128, (Bn * Tn) / 128);
        gemm_nt_bias<0><<<g, 256>>>(x, nullptr, nullptr, nullptr,
                                    Bn * Tn, En, Cn, SCALE_F);
    }
    // K/V = context @ w^T + b -> g_K / g_V   [8192,512], K=512
    {
        dim3 g(En / 128, (Bn * Sn) / 128);
        gemm_nt_bias<1><<<g, 256>>>(context, wk, bk, nullptr,
                                    Bn * Sn, En, En, 1.f);
        gemm_nt_bias<2><<<g, 256>>>(context, wv, bv, nullptr,
                                    Bn * Sn, En, En, 1.f);
    }
    // attention (tensor-core MMA, 128 q-rows/block, in place over g_Q)
    {
        const int smem_bytes =
            (2 * 64 * KPITCH + 2 * 64 * VPITCH + AWARPS * 16 * KPITCH) * 4;  // 106496
        cudaFuncSetAttribute(attn_mma_kernel,
                             cudaFuncAttributeMaxDynamicSharedMemorySize,
                             smem_bytes);
        dim3 g(Tn / QROWS, Bn * Hn);
        attn_mma_kernel<<<g, 32 * AWARPS, smem_bytes>>>(pmask);
    }
    // out = O @ w_out^T + b_out   [8192,256], K=512
    {
        dim3 g(Cn / 128, (Bn * Tn) / 128);
        gemm_nt_bias<3><<<g, 256>>>(nullptr, w_out, b_out, out,
                                    Bn * Tn, Cn, En, 1.f);
    }
}